// round 1
// baseline (speedup 1.0000x reference)
#include <cuda_runtime.h>
#include <math.h>

// Problem constants
#define NB 4
#define LL 8192
#define SS 8192
#define DD 256
#define HH 8
#define DHD 32
#define MROWS (NB * LL)   // 32768

// ---------------- scratch (static device globals; no runtime alloc) --------
__device__ float g_qfeat[MROWS * DD];
__device__ float g_kfeat[MROWS * DD];
__device__ float g_vfeat[MROWS * DD];
__device__ float g_attn [MROWS * DD];
__device__ float g_msg  [MROWS * DD];
__device__ float g_msgln[MROWS * DD];
__device__ float g_hbuf [MROWS * 2 * DD];
__device__ float g_msg2 [MROWS * DD];
__device__ float g_KV   [NB * HH * DHD * DHD];
__device__ float g_Ksum [NB * HH * DHD];

// ---------------- SGEMM: 128x128 block tile, 8x8 per-thread ---------------
#define BM 128
#define BN 128
#define BK 8
#define TM 8
#define TN 8

// EPI: 0 = none, 1 = elu(x)+1, 2 = leaky relu 0.1
template <int EPI>
__device__ __forceinline__ float epi_apply(float v) {
    if (EPI == 1) return v > 0.f ? v + 1.f : expf(v);
    if (EPI == 2) return v >= 0.f ? v : 0.1f * v;
    return v;
}

template <int EPI>
__global__ __launch_bounds__(256)
void sgemm_kernel(const float* __restrict__ A, const float* __restrict__ B,
                  float* __restrict__ C, int M, int N, int K) {
    __shared__ float As[BK][BM];
    __shared__ float Bs[BK][BN];
    const int tid = threadIdx.x;
    const int brow = blockIdx.y * BM;
    const int bcol = blockIdx.x * BN;
    const int tcol = tid & 15;       // 0..15
    const int trow = tid >> 4;       // 0..15
    const int rowA = tid >> 1;       // 0..127
    const int colA = (tid & 1) * 4;  // 0 or 4
    const int rowB = tid >> 5;       // 0..7
    const int colB = (tid & 31) * 4; // 0..124

    float acc[TM][TN];
#pragma unroll
    for (int i = 0; i < TM; i++)
#pragma unroll
        for (int j = 0; j < TN; j++) acc[i][j] = 0.f;

    for (int k0 = 0; k0 < K; k0 += BK) {
        float4 a = *reinterpret_cast<const float4*>(&A[(size_t)(brow + rowA) * K + k0 + colA]);
        As[colA + 0][rowA] = a.x;
        As[colA + 1][rowA] = a.y;
        As[colA + 2][rowA] = a.z;
        As[colA + 3][rowA] = a.w;
        *reinterpret_cast<float4*>(&Bs[rowB][colB]) =
            *reinterpret_cast<const float4*>(&B[(size_t)(k0 + rowB) * N + bcol + colB]);
        __syncthreads();
#pragma unroll
        for (int kk = 0; kk < BK; kk++) {
            float ra[TM], rb[TN];
#pragma unroll
            for (int i = 0; i < TM; i++) ra[i] = As[kk][trow * TM + i];
#pragma unroll
            for (int j = 0; j < TN; j++) rb[j] = Bs[kk][tcol * TN + j];
#pragma unroll
            for (int i = 0; i < TM; i++)
#pragma unroll
                for (int j = 0; j < TN; j++) acc[i][j] += ra[i] * rb[j];
        }
        __syncthreads();
    }
#pragma unroll
    for (int i = 0; i < TM; i++) {
        const int r = brow + trow * TM + i;
#pragma unroll
        for (int j = 0; j < TN; j += 4) {
            float4 v;
            v.x = epi_apply<EPI>(acc[i][j + 0]);
            v.y = epi_apply<EPI>(acc[i][j + 1]);
            v.z = epi_apply<EPI>(acc[i][j + 2]);
            v.w = epi_apply<EPI>(acc[i][j + 3]);
            *reinterpret_cast<float4*>(&C[(size_t)r * N + bcol + tcol * TN + j]) = v;
        }
    }
}

// concat([x, msgln]) @ W1 with leaky epilogue. K = 512, first 256 k from x,
// next 256 from msgln (both stored as [M,256]).
__global__ __launch_bounds__(256)
void sgemm_concat_kernel(const float* __restrict__ Ax, const float* __restrict__ Am,
                         const float* __restrict__ B, float* __restrict__ C,
                         int M, int N, int K) {
    __shared__ float As[BK][BM];
    __shared__ float Bs[BK][BN];
    const int tid = threadIdx.x;
    const int brow = blockIdx.y * BM;
    const int bcol = blockIdx.x * BN;
    const int tcol = tid & 15;
    const int trow = tid >> 4;
    const int rowA = tid >> 1;
    const int colA = (tid & 1) * 4;
    const int rowB = tid >> 5;
    const int colB = (tid & 31) * 4;

    float acc[TM][TN];
#pragma unroll
    for (int i = 0; i < TM; i++)
#pragma unroll
        for (int j = 0; j < TN; j++) acc[i][j] = 0.f;

    for (int k0 = 0; k0 < K; k0 += BK) {
        const int kg = k0 + colA;
        const float* src = (kg < DD) ? &Ax[(size_t)(brow + rowA) * DD + kg]
                                     : &Am[(size_t)(brow + rowA) * DD + (kg - DD)];
        float4 a = *reinterpret_cast<const float4*>(src);
        As[colA + 0][rowA] = a.x;
        As[colA + 1][rowA] = a.y;
        As[colA + 2][rowA] = a.z;
        As[colA + 3][rowA] = a.w;
        *reinterpret_cast<float4*>(&Bs[rowB][colB]) =
            *reinterpret_cast<const float4*>(&B[(size_t)(k0 + rowB) * N + bcol + colB]);
        __syncthreads();
#pragma unroll
        for (int kk = 0; kk < BK; kk++) {
            float ra[TM], rb[TN];
#pragma unroll
            for (int i = 0; i < TM; i++) ra[i] = As[kk][trow * TM + i];
#pragma unroll
            for (int j = 0; j < TN; j++) rb[j] = Bs[kk][tcol * TN + j];
#pragma unroll
            for (int i = 0; i < TM; i++)
#pragma unroll
                for (int j = 0; j < TN; j++) acc[i][j] += ra[i] * rb[j];
        }
        __syncthreads();
    }
#pragma unroll
    for (int i = 0; i < TM; i++) {
        const int r = brow + trow * TM + i;
#pragma unroll
        for (int j = 0; j < TN; j += 4) {
            float4 v;
            v.x = epi_apply<2>(acc[i][j + 0]);
            v.y = epi_apply<2>(acc[i][j + 1]);
            v.z = epi_apply<2>(acc[i][j + 2]);
            v.w = epi_apply<2>(acc[i][j + 3]);
            *reinterpret_cast<float4*>(&C[(size_t)r * N + bcol + tcol * TN + j]) = v;
        }
    }
}

// ---------------- KV = K^T V per (n,h), Ksum = sum_s K ---------------------
// One block per (n,h): deterministic accumulation over S.
__global__ __launch_bounds__(256)
void kv_kernel() {
    const int n = blockIdx.x;
    const int h = blockIdx.y;
    const float* Kf = g_kfeat + (size_t)n * LL * DD + h * DHD;
    const float* Vf = g_vfeat + (size_t)n * LL * DD + h * DHD;
    __shared__ float Ks[64][DHD];
    __shared__ float Vs[64][DHD];
    const int tid = threadIdx.x;
    const int d  = tid >> 3;        // 0..31
    const int v0 = (tid & 7) * 4;   // 0..28
    float acc0 = 0.f, acc1 = 0.f, acc2 = 0.f, acc3 = 0.f;
    float ksum = 0.f;

    for (int s0 = 0; s0 < SS; s0 += 64) {
#pragma unroll
        for (int i = 0; i < 2; i++) {
            const int f = tid * 2 + i;      // 0..511
            const int r = f >> 3;           // 0..63
            const int c4 = (f & 7) * 4;     // 0..28
            *reinterpret_cast<float4*>(&Ks[r][c4]) =
                *reinterpret_cast<const float4*>(&Kf[(size_t)(s0 + r) * DD + c4]);
            *reinterpret_cast<float4*>(&Vs[r][c4]) =
                *reinterpret_cast<const float4*>(&Vf[(size_t)(s0 + r) * DD + c4]);
        }
        __syncthreads();
#pragma unroll 8
        for (int s = 0; s < 64; s++) {
            const float kv = Ks[s][d];
            float4 vv = *reinterpret_cast<const float4*>(&Vs[s][v0]);
            acc0 += kv * vv.x;
            acc1 += kv * vv.y;
            acc2 += kv * vv.z;
            acc3 += kv * vv.w;
            ksum += kv;
        }
        __syncthreads();
    }
    float* KVout = g_KV + ((size_t)n * HH + h) * DHD * DHD;
    KVout[d * DHD + v0 + 0] = acc0;
    KVout[d * DHD + v0 + 1] = acc1;
    KVout[d * DHD + v0 + 2] = acc2;
    KVout[d * DHD + v0 + 3] = acc3;
    if ((tid & 7) == 0) g_Ksum[((size_t)n * HH + h) * DHD + d] = ksum;
}

// ---------------- per-token message: attn = Z * (Q @ KV) -------------------
// Block handles 8 tokens (one warp each); KV[n] + Ksum[n] cached in smem.
__global__ __launch_bounds__(256)
void attn_kernel() {
    __shared__ float KVs[HH * DHD * DHD];  // 32 KB
    __shared__ float Kss[HH * DHD];
    const int tid = threadIdx.x;
    const int tok0 = blockIdx.x * 8;
    const int n = tok0 / LL;
    const float* KVg = g_KV + (size_t)n * HH * DHD * DHD;
    for (int i = tid; i < HH * DHD * DHD; i += 256) KVs[i] = KVg[i];
    for (int i = tid; i < HH * DHD; i += 256) Kss[i] = g_Ksum[(size_t)n * HH * DHD + i];
    __syncthreads();

    const int warp = tid >> 5, lane = tid & 31;
    const int tok = tok0 + warp;
    const float* Q = g_qfeat + (size_t)tok * DD;
    float q[HH];
#pragma unroll
    for (int h = 0; h < HH; h++) q[h] = Q[h * DHD + lane];

    float* O = g_attn + (size_t)tok * DD;
#pragma unroll
    for (int h = 0; h < HH; h++) {
        float p = q[h] * Kss[h * DHD + lane];
#pragma unroll
        for (int o = 16; o > 0; o >>= 1) p += __shfl_xor_sync(0xffffffffu, p, o);
        const float z = 1.f / (p + 1e-6f);
        float acc = 0.f;
#pragma unroll
        for (int dd = 0; dd < DHD; dd++)
            acc += __shfl_sync(0xffffffffu, q[h], dd) * KVs[h * DHD * DHD + dd * DHD + lane];
        O[h * DHD + lane] = acc * z;
    }
}

// ---------------- LayerNorm (warp per row, D=256) --------------------------
__global__ __launch_bounds__(256)
void ln_kernel(const float* __restrict__ in, const float* __restrict__ g,
               const float* __restrict__ b, float* __restrict__ out) {
    const int warp = threadIdx.x >> 5, lane = threadIdx.x & 31;
    const int row = blockIdx.x * 8 + warp;
    const float* p = in + (size_t)row * DD;
    float v[8];
    float s = 0.f, s2 = 0.f;
#pragma unroll
    for (int i = 0; i < 8; i++) {
        v[i] = p[i * 32 + lane];
        s += v[i];
        s2 += v[i] * v[i];
    }
#pragma unroll
    for (int o = 16; o > 0; o >>= 1) {
        s  += __shfl_xor_sync(0xffffffffu, s, o);
        s2 += __shfl_xor_sync(0xffffffffu, s2, o);
    }
    const float mean = s * (1.f / DD);
    const float var = s2 * (1.f / DD) - mean * mean;
    const float rs = rsqrtf(var + 1e-5f);
    float* o2 = out + (size_t)row * DD;
#pragma unroll
    for (int i = 0; i < 8; i++) {
        const int c = i * 32 + lane;
        o2[c] = (v[i] - mean) * rs * g[c] + b[c];
    }
}

// LN2 + residual: out = x + LN(in)
__global__ __launch_bounds__(256)
void ln_res_kernel(const float* __restrict__ in, const float* __restrict__ g,
                   const float* __restrict__ b, const float* __restrict__ x,
                   float* __restrict__ out) {
    const int warp = threadIdx.x >> 5, lane = threadIdx.x & 31;
    const int row = blockIdx.x * 8 + warp;
    const float* p = in + (size_t)row * DD;
    float v[8];
    float s = 0.f, s2 = 0.f;
#pragma unroll
    for (int i = 0; i < 8; i++) {
        v[i] = p[i * 32 + lane];
        s += v[i];
        s2 += v[i] * v[i];
    }
#pragma unroll
    for (int o = 16; o > 0; o >>= 1) {
        s  += __shfl_xor_sync(0xffffffffu, s, o);
        s2 += __shfl_xor_sync(0xffffffffu, s2, o);
    }
    const float mean = s * (1.f / DD);
    const float var = s2 * (1.f / DD) - mean * mean;
    const float rs = rsqrtf(var + 1e-5f);
    const float* xr = x + (size_t)row * DD;
    float* o2 = out + (size_t)row * DD;
#pragma unroll
    for (int i = 0; i < 8; i++) {
        const int c = i * 32 + lane;
        o2[c] = xr[c] + (v[i] - mean) * rs * g[c] + b[c];
    }
}

// ---------------- launch ---------------------------------------------------
extern "C" void kernel_launch(void* const* d_in, const int* in_sizes, int n_in,
                              void* d_out, int out_size) {
    const float* x   = (const float*)d_in[0];
    const float* src = (const float*)d_in[1];
    const float* Wq  = (const float*)d_in[2];
    const float* Wk  = (const float*)d_in[3];
    const float* Wv  = (const float*)d_in[4];
    const float* Wm  = (const float*)d_in[5];
    const float* W1  = (const float*)d_in[6];
    const float* W2  = (const float*)d_in[7];
    const float* g1  = (const float*)d_in[8];
    const float* b1  = (const float*)d_in[9];
    const float* g2  = (const float*)d_in[10];
    const float* b2  = (const float*)d_in[11];
    float* out = (float*)d_out;

    float* qfeat; cudaGetSymbolAddress((void**)&qfeat, g_qfeat);
    float* kfeat; cudaGetSymbolAddress((void**)&kfeat, g_kfeat);
    float* vfeat; cudaGetSymbolAddress((void**)&vfeat, g_vfeat);
    float* attn;  cudaGetSymbolAddress((void**)&attn,  g_attn);
    float* msg;   cudaGetSymbolAddress((void**)&msg,   g_msg);
    float* msgln; cudaGetSymbolAddress((void**)&msgln, g_msgln);
    float* hbuf;  cudaGetSymbolAddress((void**)&hbuf,  g_hbuf);
    float* msg2;  cudaGetSymbolAddress((void**)&msg2,  g_msg2);

    dim3 g256(DD / BN, MROWS / BM);      // (2, 256)
    dim3 g512(2 * DD / BN, MROWS / BM);  // (4, 256)

    // Q/K features (elu+1) and V
    sgemm_kernel<1><<<g256, 256>>>(x,   Wq, qfeat, MROWS, DD, DD);
    sgemm_kernel<1><<<g256, 256>>>(src, Wk, kfeat, MROWS, DD, DD);
    sgemm_kernel<0><<<g256, 256>>>(src, Wv, vfeat, MROWS, DD, DD);
    // KV + Ksum
    kv_kernel<<<dim3(NB, HH), 256>>>();
    // per-token message
    attn_kernel<<<MROWS / 8, 256>>>();
    // merge heads + LN1
    sgemm_kernel<0><<<g256, 256>>>(attn, Wm, msg, MROWS, DD, DD);
    ln_kernel<<<MROWS / 8, 256>>>(msg, g1, b1, msgln);
    // MLP: concat -> W1 (leaky) -> W2 -> LN2 + residual
    sgemm_concat_kernel<<<g512, 256>>>(x, msgln, W1, hbuf, MROWS, 2 * DD, 2 * DD);
    sgemm_kernel<0><<<g256, 256>>>(hbuf, W2, msg2, MROWS, DD, 2 * DD);
    ln_res_kernel<<<MROWS / 8, 256>>>(msg2, g2, b2, x, out);
}

// round 3
// speedup vs baseline: 2.1286x; 2.1286x over previous
#include <cuda_runtime.h>
#include <cuda_bf16.h>
#include <math.h>
#include <stdint.h>

// Problem constants
#define NB 4
#define LL 8192
#define DD 256
#define HH 8
#define DHD 32
#define MROWS (NB * LL)   // 32768
#define KSPLIT 32

// ---------------- scratch (static device globals) --------------------------
__device__ float g_qfeat[MROWS * DD];
__device__ float g_kfeat[MROWS * DD];
__device__ float g_vfeat[MROWS * DD];
__device__ float g_attn [MROWS * DD];
__device__ float g_msgln[MROWS * DD];
__device__ float g_hbuf [MROWS * 2 * DD];
__device__ float g_KV   [NB * HH * DHD * DHD];
__device__ float g_Ksum [NB * HH * DHD];
__device__ float g_KVp  [NB * HH * KSPLIT * DHD * DHD];
__device__ float g_Ksp  [NB * HH * KSPLIT * DHD];

// ---------------- helpers --------------------------------------------------
__device__ __forceinline__ uint32_t smem_u32(const void* p) {
    uint32_t a;
    asm("{ .reg .u64 t; cvta.to.shared.u64 t, %1; cvt.u32.u64 %0, t; }" : "=r"(a) : "l"(p));
    return a;
}
__device__ __forceinline__ void ldsm4(uint32_t* r, uint32_t addr) {
    asm volatile("ldmatrix.sync.aligned.m8n8.x4.shared.b16 {%0,%1,%2,%3}, [%4];"
                 : "=r"(r[0]), "=r"(r[1]), "=r"(r[2]), "=r"(r[3]) : "r"(addr));
}
__device__ __forceinline__ void mma16816(float* c, const uint32_t* a, uint32_t b0, uint32_t b1) {
    asm volatile(
        "mma.sync.aligned.m16n8k16.row.col.f32.bf16.bf16.f32 "
        "{%0,%1,%2,%3}, {%4,%5,%6,%7}, {%8,%9}, {%0,%1,%2,%3};"
        : "+f"(c[0]), "+f"(c[1]), "+f"(c[2]), "+f"(c[3])
        : "r"(a[0]), "r"(a[1]), "r"(a[2]), "r"(a[3]), "r"(b0), "r"(b1));
}
// split fp32 -> bf16 hi + bf16 lo, packing 8 consecutive values into uint4 each
__device__ __forceinline__ void cvt8(const float* f, uint4& hi, uint4& lo) {
    uint32_t h[4], l[4];
#pragma unroll
    for (int i = 0; i < 4; i++) {
        float f0 = f[2 * i], f1 = f[2 * i + 1];
        __nv_bfloat16 h0 = __float2bfloat16_rn(f0), h1 = __float2bfloat16_rn(f1);
        float r0 = f0 - __bfloat162float(h0);
        float r1 = f1 - __bfloat162float(h1);
        __nv_bfloat16 l0 = __float2bfloat16_rn(r0), l1 = __float2bfloat16_rn(r1);
        h[i] = (uint32_t)__bfloat16_as_ushort(h0) | ((uint32_t)__bfloat16_as_ushort(h1) << 16);
        l[i] = (uint32_t)__bfloat16_as_ushort(l0) | ((uint32_t)__bfloat16_as_ushort(l1) << 16);
    }
    hi = make_uint4(h[0], h[1], h[2], h[3]);
    lo = make_uint4(l[0], l[1], l[2], l[3]);
}

// smem layout per pipeline stage (48KB): Ah 8K | Al 8K | Bh 16K | Bl 16K
#define STG 49152
#define OFF_AL 8192
#define OFF_BH 16384
#define OFF_BL 32768
#define STAGE_F 260          // epilogue staging row stride (floats)
#define EX_OFF 133120        // after 128*260*4 staging bytes
#define SMEM_ALLOC 134400

// swizzled byte offset within a 64B row: row r, 16B chunk c (0..3)
__device__ __forceinline__ uint32_t swz(int r, int c) {
    return (uint32_t)(r * 64 + ((c ^ ((r >> 1) & 3)) << 4));
}

// ---------------- mma.sync split-bf16 GEMM ---------------------------------
// C[128 x 256 tile] = A[M,K] @ W[K,N]; EPI: 0 none, 1 elu+1, 2 leaky,
// 3 LayerNorm(g,b), 4 LayerNorm + residual x
template <int EPI, bool CONCAT>
__global__ __launch_bounds__(512, 1)
void gemm_mma(const float* __restrict__ A, const float* __restrict__ A2,
              const float* __restrict__ W, float* __restrict__ C,
              int kTot, int aStride, int nFull,
              const float* __restrict__ g, const float* __restrict__ b,
              const float* __restrict__ xres) {
    extern __shared__ char smem[];
    const uint32_t sb = smem_u32(smem);
    const int t = threadIdx.x, lane = t & 31, wid = t >> 5;
    const int wm = wid & 3, wn = wid >> 2;       // 4 x 4 warp grid
    const int mrow0 = blockIdx.x * 128;
    const int bcol = blockIdx.y * 256;

    float acc[2][8][4];
#pragma unroll
    for (int i = 0; i < 2; i++)
#pragma unroll
        for (int j = 0; j < 8; j++)
#pragma unroll
            for (int q = 0; q < 4; q++) acc[i][j][q] = 0.f;

    // loader thread mapping
    const int ar = t >> 2, akq = t & 3;          // A: row, k-quarter(8 floats)
    const int bn = t & 255, bkh = t >> 8;        // B: col n, k-half(16 floats)

    float aP[8], bP[16];
    // ---- prologue: load + store chunk 0 ----
    {
        const float* srcA = (CONCAT ? A : A) ;
        const float* sA = CONCAT ? (A + (size_t)(mrow0 + ar) * 256 + akq * 8)
                                 : (A + (size_t)(mrow0 + ar) * aStride + akq * 8);
        float4 v0 = *(const float4*)sA;
        float4 v1 = *(const float4*)(sA + 4);
        aP[0]=v0.x; aP[1]=v0.y; aP[2]=v0.z; aP[3]=v0.w;
        aP[4]=v1.x; aP[5]=v1.y; aP[6]=v1.z; aP[7]=v1.w;
        const float* wp = W + (size_t)(bkh * 16) * nFull + bcol + bn;
#pragma unroll
        for (int j = 0; j < 16; j++) bP[j] = wp[(size_t)j * nFull];
        (void)srcA;
    }
    {
        uint4 hi, lo;
        cvt8(aP, hi, lo);
        *(uint4*)(smem + swz(ar, akq)) = hi;
        *(uint4*)(smem + OFF_AL + swz(ar, akq)) = lo;
#pragma unroll
        for (int jj = 0; jj < 2; jj++) {
            cvt8(bP + jj * 8, hi, lo);
            *(uint4*)(smem + OFF_BH + swz(bn, bkh * 2 + jj)) = hi;
            *(uint4*)(smem + OFF_BL + swz(bn, bkh * 2 + jj)) = lo;
        }
    }
    __syncthreads();

    const int NC = kTot >> 5;
    const int lr = lane & 15, lh = lane >> 4;

    for (int ic = 0; ic < NC; ic++) {
        const int s = ic & 1;
        const bool more = (ic + 1 < NC);
        // prefetch next chunk into regs
        if (more) {
            const int k0 = (ic + 1) * 32;
            const float* sA;
            if (CONCAT)
                sA = ((k0 < 256) ? A : A2) + (size_t)(mrow0 + ar) * 256 + (k0 & 255) + akq * 8;
            else
                sA = A + (size_t)(mrow0 + ar) * aStride + k0 + akq * 8;
            float4 v0 = *(const float4*)sA;
            float4 v1 = *(const float4*)(sA + 4);
            aP[0]=v0.x; aP[1]=v0.y; aP[2]=v0.z; aP[3]=v0.w;
            aP[4]=v1.x; aP[5]=v1.y; aP[6]=v1.z; aP[7]=v1.w;
            const float* wp = W + (size_t)(k0 + bkh * 16) * nFull + bcol + bn;
#pragma unroll
            for (int j = 0; j < 16; j++) bP[j] = wp[(size_t)j * nFull];
        }
        // ---- mma over stage s ----
        const uint32_t sA32 = sb + s * STG;
        const uint32_t sB32 = sA32 + OFF_BH;
#pragma unroll
        for (int ks = 0; ks < 2; ks++) {
            uint32_t Ah[2][4], Al[2][4], Bf[4][4];
#pragma unroll
            for (int i = 0; i < 2; i++) {
                const int r = wm * 32 + i * 16 + lr;
                const uint32_t o = swz(r, ks * 2 + lh);
                ldsm4(Ah[i], sA32 + o);
                ldsm4(Al[i], sA32 + OFF_AL + o);
            }
#pragma unroll
            for (int j2 = 0; j2 < 4; j2++) {
                const int n = wn * 64 + j2 * 16 + lr;
                ldsm4(Bf[j2], sB32 + swz(n, ks * 2 + lh));
            }
#pragma unroll
            for (int i = 0; i < 2; i++)
#pragma unroll
                for (int j2 = 0; j2 < 4; j2++) {
                    mma16816(acc[i][2 * j2 + 0], Ah[i], Bf[j2][0], Bf[j2][2]);
                    mma16816(acc[i][2 * j2 + 1], Ah[i], Bf[j2][1], Bf[j2][3]);
                }
#pragma unroll
            for (int i = 0; i < 2; i++)
#pragma unroll
                for (int j2 = 0; j2 < 4; j2++) {
                    mma16816(acc[i][2 * j2 + 0], Al[i], Bf[j2][0], Bf[j2][2]);
                    mma16816(acc[i][2 * j2 + 1], Al[i], Bf[j2][1], Bf[j2][3]);
                }
#pragma unroll
            for (int j2 = 0; j2 < 4; j2++) {
                const int n = wn * 64 + j2 * 16 + lr;
                ldsm4(Bf[j2], sB32 + (OFF_BL - OFF_BH) + swz(n, ks * 2 + lh));
            }
#pragma unroll
            for (int i = 0; i < 2; i++)
#pragma unroll
                for (int j2 = 0; j2 < 4; j2++) {
                    mma16816(acc[i][2 * j2 + 0], Ah[i], Bf[j2][0], Bf[j2][2]);
                    mma16816(acc[i][2 * j2 + 1], Ah[i], Bf[j2][1], Bf[j2][3]);
                }
        }
        // ---- store prefetched chunk into the other stage ----
        if (more) {
            char* dst = smem + (s ^ 1) * STG;
            uint4 hi, lo;
            cvt8(aP, hi, lo);
            *(uint4*)(dst + swz(ar, akq)) = hi;
            *(uint4*)(dst + OFF_AL + swz(ar, akq)) = lo;
#pragma unroll
            for (int jj = 0; jj < 2; jj++) {
                cvt8(bP + jj * 8, hi, lo);
                *(uint4*)(dst + OFF_BH + swz(bn, bkh * 2 + jj)) = hi;
                *(uint4*)(dst + OFF_BL + swz(bn, bkh * 2 + jj)) = lo;
            }
        }
        __syncthreads();
    }

    // ---- epilogue: frags -> smem staging ----
    float* stage = (float*)smem;
    {
        const int lr4 = lane >> 2, lc = (lane & 3) * 2;
#pragma unroll
        for (int i = 0; i < 2; i++) {
            const int r = wm * 32 + i * 16 + lr4;
#pragma unroll
            for (int j = 0; j < 8; j++) {
                const int c = wn * 64 + j * 8 + lc;
                *(float2*)&stage[r * STAGE_F + c] = make_float2(acc[i][j][0], acc[i][j][1]);
                *(float2*)&stage[(r + 8) * STAGE_F + c] = make_float2(acc[i][j][2], acc[i][j][3]);
            }
        }
    }
    __syncthreads();

    float* meanA = (float*)(smem + EX_OFF);
    float* rstdA = (float*)(smem + EX_OFF + 512);
    if (EPI >= 3) {
        if (t < 128) {
            float s1 = 0.f, s2 = 0.f;
#pragma unroll 8
            for (int c = 0; c < 256; c += 4) {
                float4 v = *(float4*)(stage + t * STAGE_F + c);
                s1 += v.x + v.y + v.z + v.w;
                s2 += v.x * v.x + v.y * v.y + v.z * v.z + v.w * v.w;
            }
            const float m = s1 * (1.f / 256.f);
            const float var = s2 * (1.f / 256.f) - m * m;
            meanA[t] = m;
            rstdA[t] = rsqrtf(var + 1e-5f);
        }
        __syncthreads();
    }

    // coalesced output
#pragma unroll 4
    for (int q = 0; q < 16; q++) {
        const int f = q * 512 + t;
        const int r = f >> 6, c = (f & 63) * 4;
        float4 v = *(float4*)(stage + r * STAGE_F + c);
        if (EPI == 1) {
            v.x = v.x > 0.f ? v.x + 1.f : expf(v.x);
            v.y = v.y > 0.f ? v.y + 1.f : expf(v.y);
            v.z = v.z > 0.f ? v.z + 1.f : expf(v.z);
            v.w = v.w > 0.f ? v.w + 1.f : expf(v.w);
        } else if (EPI == 2) {
            v.x = v.x >= 0.f ? v.x : 0.1f * v.x;
            v.y = v.y >= 0.f ? v.y : 0.1f * v.y;
            v.z = v.z >= 0.f ? v.z : 0.1f * v.z;
            v.w = v.w >= 0.f ? v.w : 0.1f * v.w;
        } else if (EPI >= 3) {
            const float m = meanA[r], rs = rstdA[r];
            float4 gv = *(const float4*)(g + bcol + c);
            float4 bv = *(const float4*)(b + bcol + c);
            v.x = (v.x - m) * rs * gv.x + bv.x;
            v.y = (v.y - m) * rs * gv.y + bv.y;
            v.z = (v.z - m) * rs * gv.z + bv.z;
            v.w = (v.w - m) * rs * gv.w + bv.w;
            if (EPI == 4) {
                float4 xr = *(const float4*)(xres + (size_t)(mrow0 + r) * 256 + c);
                v.x += xr.x; v.y += xr.y; v.z += xr.z; v.w += xr.w;
            }
        }
        *(float4*)(C + (size_t)(mrow0 + r) * nFull + bcol + c) = v;
    }
}

// ---------------- KV partial: split S over 32 chunks -----------------------
__global__ __launch_bounds__(256)
void kv_part() {
    const int n = blockIdx.x, h = blockIdx.y, z = blockIdx.z;
    const float* Kf = g_kfeat + (size_t)n * LL * DD + h * DHD;
    const float* Vf = g_vfeat + (size_t)n * LL * DD + h * DHD;
    __shared__ float Ks[64][DHD];
    __shared__ float Vs[64][DHD];
    const int tid = threadIdx.x;
    const int d = tid >> 3, v0 = (tid & 7) * 4;
    float a0 = 0.f, a1 = 0.f, a2 = 0.f, a3 = 0.f, ks = 0.f;
    const int s_beg = z * (LL / KSPLIT);
    for (int s0 = s_beg; s0 < s_beg + (LL / KSPLIT); s0 += 64) {
#pragma unroll
        for (int i = 0; i < 2; i++) {
            const int f = tid * 2 + i;
            const int r = f >> 3;
            const int c4 = (f & 7) * 4;
            *reinterpret_cast<float4*>(&Ks[r][c4]) =
                *reinterpret_cast<const float4*>(&Kf[(size_t)(s0 + r) * DD + c4]);
            *reinterpret_cast<float4*>(&Vs[r][c4]) =
                *reinterpret_cast<const float4*>(&Vf[(size_t)(s0 + r) * DD + c4]);
        }
        __syncthreads();
#pragma unroll 8
        for (int s = 0; s < 64; s++) {
            const float kv = Ks[s][d];
            float4 vv = *reinterpret_cast<const float4*>(&Vs[s][v0]);
            a0 += kv * vv.x; a1 += kv * vv.y; a2 += kv * vv.z; a3 += kv * vv.w;
            ks += kv;
        }
        __syncthreads();
    }
    const int p = (n * HH + h) * KSPLIT + z;
    float* out = g_KVp + (size_t)p * 1024;
    out[d * 32 + v0 + 0] = a0;
    out[d * 32 + v0 + 1] = a1;
    out[d * 32 + v0 + 2] = a2;
    out[d * 32 + v0 + 3] = a3;
    if ((tid & 7) == 0) g_Ksp[(size_t)p * 32 + d] = ks;
}

__global__ __launch_bounds__(256)
void kv_reduce() {
    const int bh = blockIdx.x;
    for (int idx = threadIdx.x; idx < 1024; idx += 256) {
        float s = 0.f;
#pragma unroll 8
        for (int z = 0; z < KSPLIT; z++)
            s += g_KVp[((size_t)bh * KSPLIT + z) * 1024 + idx];
        g_KV[(size_t)bh * 1024 + idx] = s;
    }
    if (threadIdx.x < 32) {
        float s = 0.f;
#pragma unroll 8
        for (int z = 0; z < KSPLIT; z++)
            s += g_Ksp[((size_t)bh * KSPLIT + z) * 32 + threadIdx.x];
        g_Ksum[bh * 32 + threadIdx.x] = s;
    }
}

// ---------------- per-token message: attn = Z * (Q @ KV) -------------------
__global__ __launch_bounds__(256)
void attn_kernel() {
    __shared__ float KVs[HH * DHD * DHD];
    __shared__ float Kss[HH * DHD];
    const int tid = threadIdx.x;
    const int tok0 = blockIdx.x * 8;
    const int n = tok0 / LL;
    const float* KVg = g_KV + (size_t)n * HH * DHD * DHD;
    for (int i = tid; i < HH * DHD * DHD; i += 256) KVs[i] = KVg[i];
    for (int i = tid; i < HH * DHD; i += 256) Kss[i] = g_Ksum[(size_t)n * HH * DHD + i];
    __syncthreads();

    const int warp = tid >> 5, lane = tid & 31;
    const int tok = tok0 + warp;
    const float* Q = g_qfeat + (size_t)tok * DD;
    float q[HH];
#pragma unroll
    for (int h = 0; h < HH; h++) q[h] = Q[h * DHD + lane];

    float* O = g_attn + (size_t)tok * DD;
#pragma unroll
    for (int h = 0; h < HH; h++) {
        float p = q[h] * Kss[h * DHD + lane];
#pragma unroll
        for (int o = 16; o > 0; o >>= 1) p += __shfl_xor_sync(0xffffffffu, p, o);
        const float z = 1.f / (p + 1e-6f);
        float acc = 0.f;
#pragma unroll
        for (int dd = 0; dd < DHD; dd++)
            acc += __shfl_sync(0xffffffffu, q[h], dd) * KVs[h * DHD * DHD + dd * DHD + lane];
        O[h * DHD + lane] = acc * z;
    }
}

// ---------------- launch ---------------------------------------------------
extern "C" void kernel_launch(void* const* d_in, const int* in_sizes, int n_in,
                              void* d_out, int out_size) {
    const float* x   = (const float*)d_in[0];
    const float* src = (const float*)d_in[1];
    const float* Wq  = (const float*)d_in[2];
    const float* Wk  = (const float*)d_in[3];
    const float* Wv  = (const float*)d_in[4];
    const float* Wm  = (const float*)d_in[5];
    const float* W1  = (const float*)d_in[6];
    const float* W2  = (const float*)d_in[7];
    const float* g1  = (const float*)d_in[8];
    const float* b1  = (const float*)d_in[9];
    const float* g2  = (const float*)d_in[10];
    const float* b2  = (const float*)d_in[11];
    float* out = (float*)d_out;

    float* qfeat; cudaGetSymbolAddress((void**)&qfeat, g_qfeat);
    float* kfeat; cudaGetSymbolAddress((void**)&kfeat, g_kfeat);
    float* vfeat; cudaGetSymbolAddress((void**)&vfeat, g_vfeat);
    float* attn;  cudaGetSymbolAddress((void**)&attn,  g_attn);
    float* msgln; cudaGetSymbolAddress((void**)&msgln, g_msgln);
    float* hbuf;  cudaGetSymbolAddress((void**)&hbuf,  g_hbuf);

    cudaFuncSetAttribute(gemm_mma<0, false>, cudaFuncAttributeMaxDynamicSharedMemorySize, SMEM_ALLOC);
    cudaFuncSetAttribute(gemm_mma<1, false>, cudaFuncAttributeMaxDynamicSharedMemorySize, SMEM_ALLOC);
    cudaFuncSetAttribute(gemm_mma<3, false>, cudaFuncAttributeMaxDynamicSharedMemorySize, SMEM_ALLOC);
    cudaFuncSetAttribute(gemm_mma<2, true>,  cudaFuncAttributeMaxDynamicSharedMemorySize, SMEM_ALLOC);
    cudaFuncSetAttribute(gemm_mma<4, false>, cudaFuncAttributeMaxDynamicSharedMemorySize, SMEM_ALLOC);

    const dim3 gA(MROWS / 128, 1);
    const dim3 gW1(MROWS / 128, 2);

    // Q/K features (elu+1), V
    gemm_mma<1, false><<<gA, 512, SMEM_ALLOC>>>(x,   nullptr, Wq, qfeat, 256, 256, 256, nullptr, nullptr, nullptr);
    gemm_mma<1, false><<<gA, 512, SMEM_ALLOC>>>(src, nullptr, Wk, kfeat, 256, 256, 256, nullptr, nullptr, nullptr);
    gemm_mma<0, false><<<gA, 512, SMEM_ALLOC>>>(src, nullptr, Wv, vfeat, 256, 256, 256, nullptr, nullptr, nullptr);
    // KV + Ksum (split + reduce, deterministic)
    kv_part<<<dim3(NB, HH, KSPLIT), 256>>>();
    kv_reduce<<<NB * HH, 256>>>();
    // per-token message
    attn_kernel<<<MROWS / 8, 256>>>();
    // merge heads + fused LN1
    gemm_mma<3, false><<<gA, 512, SMEM_ALLOC>>>(attn, nullptr, Wm, msgln, 256, 256, 256, g1, b1, nullptr);
    // concat -> W1 (leaky)
    gemm_mma<2, true><<<gW1, 512, SMEM_ALLOC>>>(x, msgln, W1, hbuf, 512, 256, 512, nullptr, nullptr, nullptr);
    // W2 + fused LN2 + residual -> out
    gemm_mma<4, false><<<gA, 512, SMEM_ALLOC>>>(hbuf, nullptr, W2, out, 512, 512, 256, g2, b2, x);
}

// round 4
// speedup vs baseline: 2.4477x; 1.1499x over previous
#include <cuda_runtime.h>
#include <cuda_bf16.h>
#include <math.h>
#include <stdint.h>

#define NB 4
#define LL 8192
#define DD 256
#define HH 8
#define DHD 32
#define MROWS (NB * LL)   // 32768
#define KSPLIT 32

typedef unsigned short ush;

// ---------------- scratch (static device globals) --------------------------
__device__ float g_qfeat[MROWS * DD];
__device__ float g_kfeat[MROWS * DD];
__device__ float g_vfeat[MROWS * DD];
__device__ float g_KV   [NB * HH * DHD * DHD];
__device__ float g_Ksum [NB * HH * DHD];
__device__ float g_KVp  [NB * HH * KSPLIT * DHD * DHD];
__device__ float g_Ksp  [NB * HH * KSPLIT * DHD];
// bf16 hi/lo pairs
__device__ ush g_xh[MROWS * DD],     g_xl[MROWS * DD];
__device__ ush g_sh[MROWS * DD],     g_sl[MROWS * DD];
__device__ ush g_ath[MROWS * DD],    g_atl[MROWS * DD];
__device__ ush g_mh[MROWS * DD],     g_ml[MROWS * DD];
__device__ ush g_hbh[MROWS * 2 * DD], g_hbl[MROWS * 2 * DD];
// transposed weights [N][K] bf16 hi/lo
__device__ ush g_Bqh[DD * DD], g_Bql[DD * DD];
__device__ ush g_Bkh[DD * DD], g_Bkl[DD * DD];
__device__ ush g_Bvh[DD * DD], g_Bvl[DD * DD];
__device__ ush g_Bmh[DD * DD], g_Bml[DD * DD];
__device__ ush g_B1h[2 * DD * 2 * DD], g_B1l[2 * DD * 2 * DD];
__device__ ush g_B2h[2 * DD * DD],     g_B2l[2 * DD * DD];

// ---------------- helpers --------------------------------------------------
__device__ __forceinline__ uint32_t smem_u32(const void* p) {
    uint32_t a;
    asm("{ .reg .u64 t; cvta.to.shared.u64 t, %1; cvt.u32.u64 %0, t; }" : "=r"(a) : "l"(p));
    return a;
}
__device__ __forceinline__ void cp16(uint32_t dst, const void* src) {
    asm volatile("cp.async.cg.shared.global [%0], [%1], 16;" :: "r"(dst), "l"(src) : "memory");
}
__device__ __forceinline__ void ldsm4(uint32_t* r, uint32_t addr) {
    asm volatile("ldmatrix.sync.aligned.m8n8.x4.shared.b16 {%0,%1,%2,%3}, [%4];"
                 : "=r"(r[0]), "=r"(r[1]), "=r"(r[2]), "=r"(r[3]) : "r"(addr));
}
__device__ __forceinline__ void mma16816(float* c, const uint32_t* a, uint32_t b0, uint32_t b1) {
    asm volatile(
        "mma.sync.aligned.m16n8k16.row.col.f32.bf16.bf16.f32 "
        "{%0,%1,%2,%3}, {%4,%5,%6,%7}, {%8,%9}, {%0,%1,%2,%3};"
        : "+f"(c[0]), "+f"(c[1]), "+f"(c[2]), "+f"(c[3])
        : "r"(a[0]), "r"(a[1]), "r"(a[2]), "r"(a[3]), "r"(b0), "r"(b1));
}
__device__ __forceinline__ void split1(float v, ush& h, ush& l) {
    __nv_bfloat16 hb = __float2bfloat16_rn(v);
    float r = v - __bfloat162float(hb);
    __nv_bfloat16 lb = __float2bfloat16_rn(r);
    h = __bfloat16_as_ushort(hb);
    l = __bfloat16_as_ushort(lb);
}

// smem: stage = Ah 8K | Al 8K | Bh 16K | Bl 16K = 48KB, 3 stages
#define STG 49152
#define OFF_AL 8192
#define OFF_BH 16384
#define OFF_BL 32768
#define STAGE_F 260
#define EX_OFF 133120
#define SMEM_ALLOC 147456

__device__ __forceinline__ uint32_t swz(int r, int c) {
    return (uint32_t)(r * 64 + ((c ^ ((r >> 1) & 3)) << 4));
}

// ---------------- cp.async pipelined split-bf16 GEMM -----------------------
// EPI: 0 none, 1 elu+1, 2 leaky, 3 LN(g,b), 4 LN + residual
template <int EPI, bool CONCAT, bool OUTPAIR>
__global__ __launch_bounds__(512, 1)
void gemm_cp(const ush* __restrict__ Ah, const ush* __restrict__ Al,
             const ush* __restrict__ A2h, const ush* __restrict__ A2l,
             const ush* __restrict__ Bh, const ush* __restrict__ Bl,
             float* __restrict__ Cf, ush* __restrict__ Ch, ush* __restrict__ Cl,
             int kTot, int nFull,
             const float* __restrict__ g, const float* __restrict__ b,
             const float* __restrict__ xres) {
    extern __shared__ char smem[];
    const uint32_t sb = smem_u32(smem);
    const int t = threadIdx.x, lane = t & 31, wid = t >> 5;
    const int wm = wid & 3, wn = wid >> 2;
    const int mrow0 = blockIdx.x * 128;
    const int bcol = blockIdx.y * 256;
    const int NC = kTot >> 5;
    const int aStride = CONCAT ? 256 : kTot;

    float acc[2][8][4];
#pragma unroll
    for (int i = 0; i < 2; i++)
#pragma unroll
        for (int j = 0; j < 8; j++)
#pragma unroll
            for (int q = 0; q < 4; q++) acc[i][j][q] = 0.f;

    const int ar = t >> 2, ac = t & 3;

#define ISSUE(icv)                                                              \
    {                                                                           \
        const int _ic = (icv);                                                  \
        if (_ic < NC) {                                                         \
            const int k0 = _ic * 32;                                            \
            const uint32_t base = sb + (_ic % 3) * STG;                         \
            const ush *pah, *pal;                                               \
            int ka = k0;                                                        \
            if (CONCAT && k0 >= 256) { pah = A2h; pal = A2l; ka = k0 - 256; }   \
            else { pah = Ah; pal = Al; }                                        \
            const uint32_t da = base + swz(ar, ac);                             \
            cp16(da, pah + (size_t)(mrow0 + ar) * aStride + ka + ac * 8);       \
            cp16(da + OFF_AL, pal + (size_t)(mrow0 + ar) * aStride + ka + ac * 8); \
            _Pragma("unroll")                                                   \
            for (int _i = 0; _i < 2; _i++) {                                    \
                const int idx = t + _i * 512;                                   \
                const int rb = idx >> 2, cb = idx & 3;                          \
                const uint32_t db = base + OFF_BH + swz(rb, cb);                \
                cp16(db, Bh + (size_t)(bcol + rb) * kTot + k0 + cb * 8);        \
                cp16(db + 16384, Bl + (size_t)(bcol + rb) * kTot + k0 + cb * 8);\
            }                                                                   \
        }                                                                       \
        asm volatile("cp.async.commit_group;" ::: "memory");                    \
    }

    ISSUE(0);
    ISSUE(1);

    const int lr = lane & 15, lh = lane >> 4;
    for (int ic = 0; ic < NC; ic++) {
        ISSUE(ic + 2);
        asm volatile("cp.async.wait_group 2;" ::: "memory");
        __syncthreads();
        const uint32_t sA32 = sb + (ic % 3) * STG;
        const uint32_t sB32 = sA32 + OFF_BH;
#pragma unroll
        for (int ks = 0; ks < 2; ks++) {
            uint32_t AhF[2][4], AlF[2][4], Bf[4][4];
#pragma unroll
            for (int i = 0; i < 2; i++) {
                const int r = wm * 32 + i * 16 + lr;
                const uint32_t o = swz(r, ks * 2 + lh);
                ldsm4(AhF[i], sA32 + o);
                ldsm4(AlF[i], sA32 + OFF_AL + o);
            }
#pragma unroll
            for (int j2 = 0; j2 < 4; j2++) {
                const int n = wn * 64 + j2 * 16 + lr;
                ldsm4(Bf[j2], sB32 + swz(n, ks * 2 + lh));
            }
#pragma unroll
            for (int i = 0; i < 2; i++)
#pragma unroll
                for (int j2 = 0; j2 < 4; j2++) {
                    mma16816(acc[i][2 * j2 + 0], AhF[i], Bf[j2][0], Bf[j2][2]);
                    mma16816(acc[i][2 * j2 + 1], AhF[i], Bf[j2][1], Bf[j2][3]);
                }
#pragma unroll
            for (int i = 0; i < 2; i++)
#pragma unroll
                for (int j2 = 0; j2 < 4; j2++) {
                    mma16816(acc[i][2 * j2 + 0], AlF[i], Bf[j2][0], Bf[j2][2]);
                    mma16816(acc[i][2 * j2 + 1], AlF[i], Bf[j2][1], Bf[j2][3]);
                }
#pragma unroll
            for (int j2 = 0; j2 < 4; j2++) {
                const int n = wn * 64 + j2 * 16 + lr;
                ldsm4(Bf[j2], sB32 + 16384 + swz(n, ks * 2 + lh));
            }
#pragma unroll
            for (int i = 0; i < 2; i++)
#pragma unroll
                for (int j2 = 0; j2 < 4; j2++) {
                    mma16816(acc[i][2 * j2 + 0], AhF[i], Bf[j2][0], Bf[j2][2]);
                    mma16816(acc[i][2 * j2 + 1], AhF[i], Bf[j2][1], Bf[j2][3]);
                }
        }
        __syncthreads();
    }
#undef ISSUE

    // ---- epilogue: frags -> smem staging ----
    float* stage = (float*)smem;
    {
        const int lr4 = lane >> 2, lc = (lane & 3) * 2;
#pragma unroll
        for (int i = 0; i < 2; i++) {
            const int r = wm * 32 + i * 16 + lr4;
#pragma unroll
            for (int j = 0; j < 8; j++) {
                const int c = wn * 64 + j * 8 + lc;
                *(float2*)&stage[r * STAGE_F + c] = make_float2(acc[i][j][0], acc[i][j][1]);
                *(float2*)&stage[(r + 8) * STAGE_F + c] = make_float2(acc[i][j][2], acc[i][j][3]);
            }
        }
    }
    __syncthreads();

    float* meanA = (float*)(smem + EX_OFF);
    float* rstdA = (float*)(smem + EX_OFF + 512);
    if (EPI >= 3) {
        if (t < 128) {
            float s1 = 0.f, s2 = 0.f;
#pragma unroll 8
            for (int c = 0; c < 256; c += 4) {
                float4 v = *(float4*)(stage + t * STAGE_F + c);
                s1 += v.x + v.y + v.z + v.w;
                s2 += v.x * v.x + v.y * v.y + v.z * v.z + v.w * v.w;
            }
            const float m = s1 * (1.f / 256.f);
            const float var = s2 * (1.f / 256.f) - m * m;
            meanA[t] = m;
            rstdA[t] = rsqrtf(var + 1e-5f);
        }
        __syncthreads();
    }

#pragma unroll 4
    for (int q = 0; q < 16; q++) {
        const int f = q * 512 + t;
        const int r = f >> 6, c = (f & 63) * 4;
        float4 v = *(float4*)(stage + r * STAGE_F + c);
        if (EPI == 1) {
            v.x = v.x > 0.f ? v.x + 1.f : expf(v.x);
            v.y = v.y > 0.f ? v.y + 1.f : expf(v.y);
            v.z = v.z > 0.f ? v.z + 1.f : expf(v.z);
            v.w = v.w > 0.f ? v.w + 1.f : expf(v.w);
        } else if (EPI == 2) {
            v.x = v.x >= 0.f ? v.x : 0.1f * v.x;
            v.y = v.y >= 0.f ? v.y : 0.1f * v.y;
            v.z = v.z >= 0.f ? v.z : 0.1f * v.z;
            v.w = v.w >= 0.f ? v.w : 0.1f * v.w;
        } else if (EPI >= 3) {
            const float m = meanA[r], rs = rstdA[r];
            float4 gv = *(const float4*)(g + bcol + c);
            float4 bv = *(const float4*)(b + bcol + c);
            v.x = (v.x - m) * rs * gv.x + bv.x;
            v.y = (v.y - m) * rs * gv.y + bv.y;
            v.z = (v.z - m) * rs * gv.z + bv.z;
            v.w = (v.w - m) * rs * gv.w + bv.w;
            if (EPI == 4) {
                float4 xr = *(const float4*)(xres + (size_t)(mrow0 + r) * 256 + c);
                v.x += xr.x; v.y += xr.y; v.z += xr.z; v.w += xr.w;
            }
        }
        if (OUTPAIR) {
            ush h[4], l[4];
            split1(v.x, h[0], l[0]); split1(v.y, h[1], l[1]);
            split1(v.z, h[2], l[2]); split1(v.w, h[3], l[3]);
            const size_t o = (size_t)(mrow0 + r) * nFull + bcol + c;
            *(ushort4*)(Ch + o) = make_ushort4(h[0], h[1], h[2], h[3]);
            *(ushort4*)(Cl + o) = make_ushort4(l[0], l[1], l[2], l[3]);
        } else {
            *(float4*)(Cf + (size_t)(mrow0 + r) * nFull + bcol + c) = v;
        }
    }
}

// ---------------- conversion kernels ---------------------------------------
__global__ __launch_bounds__(256)
void conv_pair(const float* __restrict__ in, ush* __restrict__ hi,
               ush* __restrict__ lo, int n4) {
    const int i = blockIdx.x * 256 + threadIdx.x;
    if (i < n4) {
        float4 v = ((const float4*)in)[i];
        ush h[4], l[4];
        split1(v.x, h[0], l[0]); split1(v.y, h[1], l[1]);
        split1(v.z, h[2], l[2]); split1(v.w, h[3], l[3]);
        ((ushort4*)hi)[i] = make_ushort4(h[0], h[1], h[2], h[3]);
        ((ushort4*)lo)[i] = make_ushort4(l[0], l[1], l[2], l[3]);
    }
}

__global__ __launch_bounds__(256)
void conv_w(const float* __restrict__ W, ush* __restrict__ Bh,
            ush* __restrict__ Bl, int K, int N) {
    __shared__ float tile[32][33];
    const int n0 = blockIdx.x * 32, k0 = blockIdx.y * 32;
    const int tx = threadIdx.x & 31, ty = threadIdx.x >> 5;
#pragma unroll
    for (int j = 0; j < 4; j++)
        tile[ty * 4 + j][tx] = W[(size_t)(k0 + ty * 4 + j) * N + n0 + tx];
    __syncthreads();
#pragma unroll
    for (int j = 0; j < 4; j++) {
        const int nl = ty * 4 + j;
        const float v = tile[tx][nl];
        ush h, l;
        split1(v, h, l);
        Bh[(size_t)(n0 + nl) * K + k0 + tx] = h;
        Bl[(size_t)(n0 + nl) * K + k0 + tx] = l;
    }
}

// ---------------- KV partial -----------------------------------------------
__global__ __launch_bounds__(256)
void kv_part() {
    const int n = blockIdx.x, h = blockIdx.y, z = blockIdx.z;
    const float* Kf = g_kfeat + (size_t)n * LL * DD + h * DHD;
    const float* Vf = g_vfeat + (size_t)n * LL * DD + h * DHD;
    __shared__ float sh[4096];      // Ks 64x32 | Vs 64x32 (reused for reduce)
    float* Ks = sh;
    float* Vs = sh + 2048;
    const int tid = threadIdx.x;
    const int sp = tid >> 6;            // 4 substreams
    const int rem = tid & 63;
    const int d0 = (rem >> 3) * 4;      // 8 d-quads
    const int v0 = (rem & 7) * 4;       // 8 v-quads
    float acc[4][4];
    float ksm[4] = {0.f, 0.f, 0.f, 0.f};
#pragma unroll
    for (int i = 0; i < 4; i++)
#pragma unroll
        for (int j = 0; j < 4; j++) acc[i][j] = 0.f;

    const int s_beg = z * (LL / KSPLIT);
    for (int s0 = s_beg; s0 < s_beg + (LL / KSPLIT); s0 += 64) {
#pragma unroll
        for (int i = 0; i < 2; i++) {
            const int f = tid * 2 + i;
            const int r = f >> 3;
            const int c4 = (f & 7) * 4;
            *(float4*)&Ks[r * 32 + c4] = *(const float4*)&Kf[(size_t)(s0 + r) * DD + c4];
            *(float4*)&Vs[r * 32 + c4] = *(const float4*)&Vf[(size_t)(s0 + r) * DD + c4];
        }
        __syncthreads();
#pragma unroll 4
        for (int s = sp; s < 64; s += 4) {
            float4 vv = *(const float4*)&Vs[s * 32 + v0];
#pragma unroll
            for (int i = 0; i < 4; i++) {
                const float kk = Ks[s * 32 + d0 + i];
                acc[i][0] += kk * vv.x;
                acc[i][1] += kk * vv.y;
                acc[i][2] += kk * vv.z;
                acc[i][3] += kk * vv.w;
                ksm[i] += kk;
            }
        }
        __syncthreads();
    }
    // reduce across 4 substreams via smem (reuse sh: 256 x 16 floats)
    float* red = sh;
#pragma unroll
    for (int i = 0; i < 4; i++)
#pragma unroll
        for (int j = 0; j < 4; j++) red[tid * 16 + i * 4 + j] = acc[i][j];
    __syncthreads();
    const int p = (n * HH + h) * KSPLIT + z;
    if (sp == 0) {
        float* out = g_KVp + (size_t)p * 1024;
#pragma unroll
        for (int i = 0; i < 4; i++)
#pragma unroll
            for (int j = 0; j < 4; j++) {
                float s = red[rem * 16 + i * 4 + j] + red[(64 + rem) * 16 + i * 4 + j]
                        + red[(128 + rem) * 16 + i * 4 + j] + red[(192 + rem) * 16 + i * 4 + j];
                out[(d0 + i) * 32 + v0 + j] = s;
            }
    }
    __syncthreads();
#pragma unroll
    for (int i = 0; i < 4; i++) red[tid * 4 + i] = ksm[i];
    __syncthreads();
    if (sp == 0 && (rem & 7) == 0) {
#pragma unroll
        for (int i = 0; i < 4; i++) {
            float s = red[rem * 4 + i] + red[(64 + rem) * 4 + i]
                    + red[(128 + rem) * 4 + i] + red[(192 + rem) * 4 + i];
            g_Ksp[(size_t)p * 32 + d0 + i] = s;
        }
    }
}

__global__ __launch_bounds__(256)
void kv_reduce() {
    const int bh = blockIdx.x;
    for (int idx = threadIdx.x; idx < 1024; idx += 256) {
        float s = 0.f;
#pragma unroll 8
        for (int z = 0; z < KSPLIT; z++)
            s += g_KVp[((size_t)bh * KSPLIT + z) * 1024 + idx];
        g_KV[(size_t)bh * 1024 + idx] = s;
    }
    if (threadIdx.x < 32) {
        float s = 0.f;
#pragma unroll 8
        for (int z = 0; z < KSPLIT; z++)
            s += g_Ksp[((size_t)bh * KSPLIT + z) * 32 + threadIdx.x];
        g_Ksum[bh * 32 + threadIdx.x] = s;
    }
}

// ---------------- per-token message (outputs bf16 pair) --------------------
__global__ __launch_bounds__(256)
void attn_kernel() {
    __shared__ float KVs[HH * DHD * DHD];
    __shared__ float Kss[HH * DHD];
    const int tid = threadIdx.x;
    const int tok0 = blockIdx.x * 8;
    const int n = tok0 / LL;
    const float* KVg = g_KV + (size_t)n * HH * DHD * DHD;
    for (int i = tid; i < HH * DHD * DHD; i += 256) KVs[i] = KVg[i];
    for (int i = tid; i < HH * DHD; i += 256) Kss[i] = g_Ksum[(size_t)n * HH * DHD + i];
    __syncthreads();

    const int warp = tid >> 5, lane = tid & 31;
    const int tok = tok0 + warp;
    const float* Q = g_qfeat + (size_t)tok * DD;
    float q[HH];
#pragma unroll
    for (int h = 0; h < HH; h++) q[h] = Q[h * DHD + lane];

#pragma unroll
    for (int h = 0; h < HH; h++) {
        float p = q[h] * Kss[h * DHD + lane];
#pragma unroll
        for (int o = 16; o > 0; o >>= 1) p += __shfl_xor_sync(0xffffffffu, p, o);
        const float z = 1.f / (p + 1e-6f);
        float acc = 0.f;
#pragma unroll
        for (int dd = 0; dd < DHD; dd++)
            acc += __shfl_sync(0xffffffffu, q[h], dd) * KVs[h * DHD * DHD + dd * DHD + lane];
        const float val = acc * z;
        ush hb, lb;
        split1(val, hb, lb);
        g_ath[(size_t)tok * DD + h * DHD + lane] = hb;
        g_atl[(size_t)tok * DD + h * DHD + lane] = lb;
    }
}

// ---------------- launch ---------------------------------------------------
extern "C" void kernel_launch(void* const* d_in, const int* in_sizes, int n_in,
                              void* d_out, int out_size) {
    const float* x   = (const float*)d_in[0];
    const float* src = (const float*)d_in[1];
    const float* Wq  = (const float*)d_in[2];
    const float* Wk  = (const float*)d_in[3];
    const float* Wv  = (const float*)d_in[4];
    const float* Wm  = (const float*)d_in[5];
    const float* W1  = (const float*)d_in[6];
    const float* W2  = (const float*)d_in[7];
    const float* g1  = (const float*)d_in[8];
    const float* b1  = (const float*)d_in[9];
    const float* g2  = (const float*)d_in[10];
    const float* b2  = (const float*)d_in[11];
    float* out = (float*)d_out;

    float* qfeat; cudaGetSymbolAddress((void**)&qfeat, g_qfeat);
    float* kfeat; cudaGetSymbolAddress((void**)&kfeat, g_kfeat);
    float* vfeat; cudaGetSymbolAddress((void**)&vfeat, g_vfeat);
    ush *xh, *xl, *sh_, *sl, *ath, *atl, *mh, *ml, *hbh, *hbl;
    cudaGetSymbolAddress((void**)&xh, g_xh);   cudaGetSymbolAddress((void**)&xl, g_xl);
    cudaGetSymbolAddress((void**)&sh_, g_sh);  cudaGetSymbolAddress((void**)&sl, g_sl);
    cudaGetSymbolAddress((void**)&ath, g_ath); cudaGetSymbolAddress((void**)&atl, g_atl);
    cudaGetSymbolAddress((void**)&mh, g_mh);   cudaGetSymbolAddress((void**)&ml, g_ml);
    cudaGetSymbolAddress((void**)&hbh, g_hbh); cudaGetSymbolAddress((void**)&hbl, g_hbl);
    ush *Bqh, *Bql, *Bkh, *Bkl, *Bvh, *Bvl, *Bmh, *Bml, *B1h, *B1l, *B2h, *B2l;
    cudaGetSymbolAddress((void**)&Bqh, g_Bqh); cudaGetSymbolAddress((void**)&Bql, g_Bql);
    cudaGetSymbolAddress((void**)&Bkh, g_Bkh); cudaGetSymbolAddress((void**)&Bkl, g_Bkl);
    cudaGetSymbolAddress((void**)&Bvh, g_Bvh); cudaGetSymbolAddress((void**)&Bvl, g_Bvl);
    cudaGetSymbolAddress((void**)&Bmh, g_Bmh); cudaGetSymbolAddress((void**)&Bml, g_Bml);
    cudaGetSymbolAddress((void**)&B1h, g_B1h); cudaGetSymbolAddress((void**)&B1l, g_B1l);
    cudaGetSymbolAddress((void**)&B2h, g_B2h); cudaGetSymbolAddress((void**)&B2l, g_B2l);

    cudaFuncSetAttribute(gemm_cp<1, false, false>, cudaFuncAttributeMaxDynamicSharedMemorySize, SMEM_ALLOC);
    cudaFuncSetAttribute(gemm_cp<0, false, false>, cudaFuncAttributeMaxDynamicSharedMemorySize, SMEM_ALLOC);
    cudaFuncSetAttribute(gemm_cp<3, false, true>,  cudaFuncAttributeMaxDynamicSharedMemorySize, SMEM_ALLOC);
    cudaFuncSetAttribute(gemm_cp<2, true, true>,   cudaFuncAttributeMaxDynamicSharedMemorySize, SMEM_ALLOC);
    cudaFuncSetAttribute(gemm_cp<4, false, false>, cudaFuncAttributeMaxDynamicSharedMemorySize, SMEM_ALLOC);

    // input / weight conversion
    const int n4 = MROWS * DD / 4;
    conv_pair<<<(n4 + 255) / 256, 256>>>(x,   xh,  xl,  n4);
    conv_pair<<<(n4 + 255) / 256, 256>>>(src, sh_, sl,  n4);
    conv_w<<<dim3(DD / 32, DD / 32), 256>>>(Wq, Bqh, Bql, DD, DD);
    conv_w<<<dim3(DD / 32, DD / 32), 256>>>(Wk, Bkh, Bkl, DD, DD);
    conv_w<<<dim3(DD / 32, DD / 32), 256>>>(Wv, Bvh, Bvl, DD, DD);
    conv_w<<<dim3(DD / 32, DD / 32), 256>>>(Wm, Bmh, Bml, DD, DD);
    conv_w<<<dim3(2 * DD / 32, 2 * DD / 32), 256>>>(W1, B1h, B1l, 2 * DD, 2 * DD);
    conv_w<<<dim3(DD / 32, 2 * DD / 32), 256>>>(W2, B2h, B2l, 2 * DD, DD);

    const dim3 gA(MROWS / 128, 1);
    const dim3 gW1(MROWS / 128, 2);

    gemm_cp<1, false, false><<<gA, 512, SMEM_ALLOC>>>(xh, xl, nullptr, nullptr, Bqh, Bql,
        qfeat, nullptr, nullptr, 256, 256, nullptr, nullptr, nullptr);
    gemm_cp<1, false, false><<<gA, 512, SMEM_ALLOC>>>(sh_, sl, nullptr, nullptr, Bkh, Bkl,
        kfeat, nullptr, nullptr, 256, 256, nullptr, nullptr, nullptr);
    gemm_cp<0, false, false><<<gA, 512, SMEM_ALLOC>>>(sh_, sl, nullptr, nullptr, Bvh, Bvl,
        vfeat, nullptr, nullptr, 256, 256, nullptr, nullptr, nullptr);

    kv_part<<<dim3(NB, HH, KSPLIT), 256>>>();
    kv_reduce<<<NB * HH, 256>>>();
    attn_kernel<<<MROWS / 8, 256>>>();

    // merge heads + fused LN1 -> msgln pair
    gemm_cp<3, false, true><<<gA, 512, SMEM_ALLOC>>>(ath, atl, nullptr, nullptr, Bmh, Bml,
        nullptr, mh, ml, 256, 256, g1, b1, nullptr);
    // concat -> W1 (leaky) -> hbuf pair
    gemm_cp<2, true, true><<<gW1, 512, SMEM_ALLOC>>>(xh, xl, mh, ml, B1h, B1l,
        nullptr, hbh, hbl, 512, 512, nullptr, nullptr, nullptr);
    // W2 + fused LN2 + residual -> out
    gemm_cp<4, false, false><<<gA, 512, SMEM_ALLOC>>>(hbh, hbl, nullptr, nullptr, B2h, B2l,
        out, nullptr, nullptr, 512, 256, g2, b2, x);
}

// round 5
// speedup vs baseline: 3.1712x; 1.2956x over previous
#include <cuda_runtime.h>
#include <cuda_fp16.h>
#include <math.h>
#include <stdint.h>

#define NB 4
#define LL 8192
#define DD 256
#define HH 8
#define DHD 32
#define MROWS (NB * LL)   // 32768
#define KSPLIT 32

typedef unsigned short ush;

// ---------------- scratch (static device globals) --------------------------
__device__ float g_qfeat[MROWS * DD];
__device__ float g_kfeat[MROWS * DD];
__device__ float g_vfeat[MROWS * DD];
__device__ float g_KV   [NB * HH * DHD * DHD];
__device__ float g_Ksum [NB * HH * DHD];
__device__ float g_KVp  [NB * HH * KSPLIT * DHD * DHD];
__device__ float g_Ksp  [NB * HH * KSPLIT * DHD];
// fp16 hi/lo pairs (A-side operands)
__device__ ush g_xh[MROWS * DD],      g_xl[MROWS * DD];
__device__ ush g_sh[MROWS * DD],      g_sl[MROWS * DD];
__device__ ush g_ath[MROWS * DD],     g_atl[MROWS * DD];
__device__ ush g_mh[MROWS * DD],      g_ml[MROWS * DD];
__device__ ush g_hbh[MROWS * 2 * DD], g_hbl[MROWS * 2 * DD];
// transposed fp16 weights [N][K]
__device__ ush g_Bqh[DD * DD];
__device__ ush g_Bkh[DD * DD];
__device__ ush g_Bvh[DD * DD];
__device__ ush g_Bmh[DD * DD];
__device__ ush g_B1h[2 * DD * 2 * DD];
__device__ ush g_B2h[2 * DD * DD];

// ---------------- helpers --------------------------------------------------
__device__ __forceinline__ uint32_t smem_u32(const void* p) {
    uint32_t a;
    asm("{ .reg .u64 t; cvta.to.shared.u64 t, %1; cvt.u32.u64 %0, t; }" : "=r"(a) : "l"(p));
    return a;
}
__device__ __forceinline__ void cp16(uint32_t dst, const void* src) {
    asm volatile("cp.async.cg.shared.global [%0], [%1], 16;" :: "r"(dst), "l"(src) : "memory");
}
__device__ __forceinline__ void ldsm4(uint32_t* r, uint32_t addr) {
    asm volatile("ldmatrix.sync.aligned.m8n8.x4.shared.b16 {%0,%1,%2,%3}, [%4];"
                 : "=r"(r[0]), "=r"(r[1]), "=r"(r[2]), "=r"(r[3]) : "r"(addr));
}
__device__ __forceinline__ void mma16816(float* c, const uint32_t* a, uint32_t b0, uint32_t b1) {
    asm volatile(
        "mma.sync.aligned.m16n8k16.row.col.f32.f16.f16.f32 "
        "{%0,%1,%2,%3}, {%4,%5,%6,%7}, {%8,%9}, {%0,%1,%2,%3};"
        : "+f"(c[0]), "+f"(c[1]), "+f"(c[2]), "+f"(c[3])
        : "r"(a[0]), "r"(a[1]), "r"(a[2]), "r"(a[3]), "r"(b0), "r"(b1));
}
__device__ __forceinline__ void split1(float v, ush& h, ush& l) {
    __half hb = __float2half_rn(v);
    float r = v - __half2float(hb);
    __half lb = __float2half_rn(r);
    h = __half_as_ushort(hb);
    l = __half_as_ushort(lb);
}

// smem: stage = Ah 16K | Al 16K | Bh 32K = 64KB, 3 stages
#define STG 65536
#define OFF_AL 16384
#define OFF_B  32768
#define STAGE_F 260
#define EX_OFF 133120
#define SMEM_ALLOC 196608

// 128B rows, 8 x 16B chunks, xor-swizzled
__device__ __forceinline__ uint32_t swz128(int r, int c) {
    return (uint32_t)(r * 128 + ((c ^ (r & 7)) << 4));
}

// ---------------- cp.async pipelined split-fp16 GEMM -----------------------
// EPI: 0 none, 1 elu+1, 2 leaky, 3 LN(g,b), 4 LN + residual
template <int EPI, bool CONCAT, bool OUTPAIR>
__global__ __launch_bounds__(512, 1)
void gemm_cp(const ush* __restrict__ Ah, const ush* __restrict__ Al,
             const ush* __restrict__ A2h, const ush* __restrict__ A2l,
             const ush* __restrict__ Bh,
             float* __restrict__ Cf, ush* __restrict__ Ch, ush* __restrict__ Cl,
             int kTot, int nFull,
             const float* __restrict__ g, const float* __restrict__ b,
             const float* __restrict__ xres) {
    extern __shared__ char smem[];
    const uint32_t sb = smem_u32(smem);
    const int t = threadIdx.x, lane = t & 31, wid = t >> 5;
    const int wm = wid & 3, wn = wid >> 2;
    const int mrow0 = blockIdx.x * 128;
    const int bcol = blockIdx.y * 256;
    const int NC = kTot >> 6;
    const int aStride = CONCAT ? 256 : kTot;

    float acc[2][8][4];
#pragma unroll
    for (int i = 0; i < 2; i++)
#pragma unroll
        for (int j = 0; j < 8; j++)
#pragma unroll
            for (int q = 0; q < 4; q++) acc[i][j][q] = 0.f;

#define ISSUE(icv)                                                               \
    {                                                                            \
        const int _ic = (icv);                                                   \
        if (_ic < NC) {                                                          \
            const int k0 = _ic * 64;                                             \
            const uint32_t base = sb + (_ic % 3) * STG;                          \
            const ush *pah, *pal;                                                \
            int ka = k0;                                                         \
            if (CONCAT && k0 >= 256) { pah = A2h; pal = A2l; ka = k0 - 256; }    \
            else { pah = Ah; pal = Al; }                                         \
            _Pragma("unroll")                                                    \
            for (int _i = 0; _i < 2; _i++) {                                     \
                const int idx = t + _i * 512;                                    \
                const int r = idx >> 3, c = idx & 7;                             \
                const uint32_t da = base + swz128(r, c);                         \
                const size_t so = (size_t)(mrow0 + r) * aStride + ka + c * 8;    \
                cp16(da, pah + so);                                              \
                cp16(da + OFF_AL, pal + so);                                     \
            }                                                                    \
            _Pragma("unroll")                                                    \
            for (int _i = 0; _i < 4; _i++) {                                     \
                const int idx = t + _i * 512;                                    \
                const int rb = idx >> 3, cb = idx & 7;                           \
                cp16(base + OFF_B + swz128(rb, cb),                              \
                     Bh + (size_t)(bcol + rb) * kTot + k0 + cb * 8);             \
            }                                                                    \
        }                                                                        \
        asm volatile("cp.async.commit_group;" ::: "memory");                     \
    }

    ISSUE(0);
    ISSUE(1);

    const int lr = lane & 15, lh = lane >> 4;
    for (int ic = 0; ic < NC; ic++) {
        asm volatile("cp.async.wait_group 1;" ::: "memory");
        __syncthreads();
        ISSUE(ic + 2);
        const uint32_t sA32 = sb + (ic % 3) * STG;
        const uint32_t sB32 = sA32 + OFF_B;
#pragma unroll
        for (int ks = 0; ks < 4; ks++) {
            uint32_t AhF[2][4], AlF[2][4], Bf[4][4];
#pragma unroll
            for (int i = 0; i < 2; i++) {
                const int r = wm * 32 + i * 16 + lr;
                const uint32_t o = swz128(r, ks * 2 + lh);
                ldsm4(AhF[i], sA32 + o);
                ldsm4(AlF[i], sA32 + OFF_AL + o);
            }
#pragma unroll
            for (int j2 = 0; j2 < 4; j2++) {
                const int n = wn * 64 + j2 * 16 + lr;
                ldsm4(Bf[j2], sB32 + swz128(n, ks * 2 + lh));
            }
#pragma unroll
            for (int i = 0; i < 2; i++)
#pragma unroll
                for (int j2 = 0; j2 < 4; j2++) {
                    mma16816(acc[i][2 * j2 + 0], AhF[i], Bf[j2][0], Bf[j2][2]);
                    mma16816(acc[i][2 * j2 + 1], AhF[i], Bf[j2][1], Bf[j2][3]);
                }
#pragma unroll
            for (int i = 0; i < 2; i++)
#pragma unroll
                for (int j2 = 0; j2 < 4; j2++) {
                    mma16816(acc[i][2 * j2 + 0], AlF[i], Bf[j2][0], Bf[j2][2]);
                    mma16816(acc[i][2 * j2 + 1], AlF[i], Bf[j2][1], Bf[j2][3]);
                }
        }
        __syncthreads();
    }
#undef ISSUE

    // ---- epilogue: frags -> smem staging ----
    float* stage = (float*)smem;
    {
        const int lr4 = lane >> 2, lc = (lane & 3) * 2;
#pragma unroll
        for (int i = 0; i < 2; i++) {
            const int r = wm * 32 + i * 16 + lr4;
#pragma unroll
            for (int j = 0; j < 8; j++) {
                const int c = wn * 64 + j * 8 + lc;
                *(float2*)&stage[r * STAGE_F + c] = make_float2(acc[i][j][0], acc[i][j][1]);
                *(float2*)&stage[(r + 8) * STAGE_F + c] = make_float2(acc[i][j][2], acc[i][j][3]);
            }
        }
    }
    __syncthreads();

    float* meanA = (float*)(smem + EX_OFF);
    float* rstdA = (float*)(smem + EX_OFF + 512);
    if (EPI >= 3) {
        if (t < 128) {
            float s1 = 0.f, s2 = 0.f;
#pragma unroll 8
            for (int c = 0; c < 256; c += 4) {
                float4 v = *(float4*)(stage + t * STAGE_F + c);
                s1 += v.x + v.y + v.z + v.w;
                s2 += v.x * v.x + v.y * v.y + v.z * v.z + v.w * v.w;
            }
            const float m = s1 * (1.f / 256.f);
            const float var = s2 * (1.f / 256.f) - m * m;
            meanA[t] = m;
            rstdA[t] = rsqrtf(var + 1e-5f);
        }
        __syncthreads();
    }

#pragma unroll 4
    for (int q = 0; q < 16; q++) {
        const int f = q * 512 + t;
        const int r = f >> 6, c = (f & 63) * 4;
        float4 v = *(float4*)(stage + r * STAGE_F + c);
        if (EPI == 1) {
            v.x = v.x > 0.f ? v.x + 1.f : expf(v.x);
            v.y = v.y > 0.f ? v.y + 1.f : expf(v.y);
            v.z = v.z > 0.f ? v.z + 1.f : expf(v.z);
            v.w = v.w > 0.f ? v.w + 1.f : expf(v.w);
        } else if (EPI == 2) {
            v.x = v.x >= 0.f ? v.x : 0.1f * v.x;
            v.y = v.y >= 0.f ? v.y : 0.1f * v.y;
            v.z = v.z >= 0.f ? v.z : 0.1f * v.z;
            v.w = v.w >= 0.f ? v.w : 0.1f * v.w;
        } else if (EPI >= 3) {
            const float m = meanA[r], rs = rstdA[r];
            float4 gv = *(const float4*)(g + bcol + c);
            float4 bv = *(const float4*)(b + bcol + c);
            v.x = (v.x - m) * rs * gv.x + bv.x;
            v.y = (v.y - m) * rs * gv.y + bv.y;
            v.z = (v.z - m) * rs * gv.z + bv.z;
            v.w = (v.w - m) * rs * gv.w + bv.w;
            if (EPI == 4) {
                float4 xr = *(const float4*)(xres + (size_t)(mrow0 + r) * 256 + c);
                v.x += xr.x; v.y += xr.y; v.z += xr.z; v.w += xr.w;
            }
        }
        if (OUTPAIR) {
            ush h[4], l[4];
            split1(v.x, h[0], l[0]); split1(v.y, h[1], l[1]);
            split1(v.z, h[2], l[2]); split1(v.w, h[3], l[3]);
            const size_t o = (size_t)(mrow0 + r) * nFull + bcol + c;
            *(ushort4*)(Ch + o) = make_ushort4(h[0], h[1], h[2], h[3]);
            *(ushort4*)(Cl + o) = make_ushort4(l[0], l[1], l[2], l[3]);
        } else {
            *(float4*)(Cf + (size_t)(mrow0 + r) * nFull + bcol + c) = v;
        }
    }
}

// ---------------- conversion kernels ---------------------------------------
__global__ __launch_bounds__(256)
void conv_pair(const float* __restrict__ in, ush* __restrict__ hi,
               ush* __restrict__ lo, int n4) {
    const int i = blockIdx.x * 256 + threadIdx.x;
    if (i < n4) {
        float4 v = ((const float4*)in)[i];
        ush h[4], l[4];
        split1(v.x, h[0], l[0]); split1(v.y, h[1], l[1]);
        split1(v.z, h[2], l[2]); split1(v.w, h[3], l[3]);
        ((ushort4*)hi)[i] = make_ushort4(h[0], h[1], h[2], h[3]);
        ((ushort4*)lo)[i] = make_ushort4(l[0], l[1], l[2], l[3]);
    }
}

__global__ __launch_bounds__(256)
void conv_w(const float* __restrict__ W, ush* __restrict__ Bh, int K, int N) {
    __shared__ float tile[32][33];
    const int n0 = blockIdx.x * 32, k0 = blockIdx.y * 32;
    const int tx = threadIdx.x & 31, ty = threadIdx.x >> 5;
#pragma unroll
    for (int j = 0; j < 4; j++)
        tile[ty * 4 + j][tx] = W[(size_t)(k0 + ty * 4 + j) * N + n0 + tx];
    __syncthreads();
#pragma unroll
    for (int j = 0; j < 4; j++) {
        const int nl = ty * 4 + j;
        Bh[(size_t)(n0 + nl) * K + k0 + tx] =
            __half_as_ushort(__float2half_rn(tile[tx][nl]));
    }
}

// ---------------- KV partial -----------------------------------------------
__global__ __launch_bounds__(256)
void kv_part() {
    const int n = blockIdx.x, h = blockIdx.y, z = blockIdx.z;
    const float* Kf = g_kfeat + (size_t)n * LL * DD + h * DHD;
    const float* Vf = g_vfeat + (size_t)n * LL * DD + h * DHD;
    __shared__ float sh[4096];
    float* Ks = sh;
    float* Vs = sh + 2048;
    const int tid = threadIdx.x;
    const int sp = tid >> 6;
    const int rem = tid & 63;
    const int d0 = (rem >> 3) * 4;
    const int v0 = (rem & 7) * 4;
    float acc[4][4];
    float ksm[4] = {0.f, 0.f, 0.f, 0.f};
#pragma unroll
    for (int i = 0; i < 4; i++)
#pragma unroll
        for (int j = 0; j < 4; j++) acc[i][j] = 0.f;

    const int s_beg = z * (LL / KSPLIT);
    for (int s0 = s_beg; s0 < s_beg + (LL / KSPLIT); s0 += 64) {
#pragma unroll
        for (int i = 0; i < 2; i++) {
            const int f = tid * 2 + i;
            const int r = f >> 3;
            const int c4 = (f & 7) * 4;
            *(float4*)&Ks[r * 32 + c4] = *(const float4*)&Kf[(size_t)(s0 + r) * DD + c4];
            *(float4*)&Vs[r * 32 + c4] = *(const float4*)&Vf[(size_t)(s0 + r) * DD + c4];
        }
        __syncthreads();
#pragma unroll 4
        for (int s = sp; s < 64; s += 4) {
            float4 vv = *(const float4*)&Vs[s * 32 + v0];
#pragma unroll
            for (int i = 0; i < 4; i++) {
                const float kk = Ks[s * 32 + d0 + i];
                acc[i][0] += kk * vv.x;
                acc[i][1] += kk * vv.y;
                acc[i][2] += kk * vv.z;
                acc[i][3] += kk * vv.w;
                ksm[i] += kk;
            }
        }
        __syncthreads();
    }
    float* red = sh;
#pragma unroll
    for (int i = 0; i < 4; i++)
#pragma unroll
        for (int j = 0; j < 4; j++) red[tid * 16 + i * 4 + j] = acc[i][j];
    __syncthreads();
    const int p = (n * HH + h) * KSPLIT + z;
    if (sp == 0) {
        float* out = g_KVp + (size_t)p * 1024;
#pragma unroll
        for (int i = 0; i < 4; i++)
#pragma unroll
            for (int j = 0; j < 4; j++) {
                float s = red[rem * 16 + i * 4 + j] + red[(64 + rem) * 16 + i * 4 + j]
                        + red[(128 + rem) * 16 + i * 4 + j] + red[(192 + rem) * 16 + i * 4 + j];
                out[(d0 + i) * 32 + v0 + j] = s;
            }
    }
    __syncthreads();
#pragma unroll
    for (int i = 0; i < 4; i++) red[tid * 4 + i] = ksm[i];
    __syncthreads();
    if (sp == 0 && (rem & 7) == 0) {
#pragma unroll
        for (int i = 0; i < 4; i++) {
            float s = red[rem * 4 + i] + red[(64 + rem) * 4 + i]
                    + red[(128 + rem) * 4 + i] + red[(192 + rem) * 4 + i];
            g_Ksp[(size_t)p * 32 + d0 + i] = s;
        }
    }
}

__global__ __launch_bounds__(256)
void kv_reduce() {
    const int bh = blockIdx.x;
    for (int idx = threadIdx.x; idx < 1024; idx += 256) {
        float s = 0.f;
#pragma unroll 8
        for (int z = 0; z < KSPLIT; z++)
            s += g_KVp[((size_t)bh * KSPLIT + z) * 1024 + idx];
        g_KV[(size_t)bh * 1024 + idx] = s;
    }
    if (threadIdx.x < 32) {
        float s = 0.f;
#pragma unroll 8
        for (int z = 0; z < KSPLIT; z++)
            s += g_Ksp[((size_t)bh * KSPLIT + z) * 32 + threadIdx.x];
        g_Ksum[bh * 32 + threadIdx.x] = s;
    }
}

// ---------------- per-token message (outputs fp16 pair) --------------------
__global__ __launch_bounds__(256)
void attn_kernel() {
    __shared__ float KVs[HH * DHD * DHD];
    __shared__ float Kss[HH * DHD];
    const int tid = threadIdx.x;
    const int tok0 = blockIdx.x * 8;
    const int n = tok0 / LL;
    const float* KVg = g_KV + (size_t)n * HH * DHD * DHD;
    for (int i = tid; i < HH * DHD * DHD; i += 256) KVs[i] = KVg[i];
    for (int i = tid; i < HH * DHD; i += 256) Kss[i] = g_Ksum[(size_t)n * HH * DHD + i];
    __syncthreads();

    const int warp = tid >> 5, lane = tid & 31;
    const int tok = tok0 + warp;
    const float* Q = g_qfeat + (size_t)tok * DD;
    float q[HH];
#pragma unroll
    for (int h = 0; h < HH; h++) q[h] = Q[h * DHD + lane];

#pragma unroll
    for (int h = 0; h < HH; h++) {
        float p = q[h] * Kss[h * DHD + lane];
#pragma unroll
        for (int o = 16; o > 0; o >>= 1) p += __shfl_xor_sync(0xffffffffu, p, o);
        const float z = 1.f / (p + 1e-6f);
        float acc = 0.f;
#pragma unroll
        for (int dd = 0; dd < DHD; dd++)
            acc += __shfl_sync(0xffffffffu, q[h], dd) * KVs[h * DHD * DHD + dd * DHD + lane];
        const float val = acc * z;
        ush hb, lb;
        split1(val, hb, lb);
        g_ath[(size_t)tok * DD + h * DHD + lane] = hb;
        g_atl[(size_t)tok * DD + h * DHD + lane] = lb;
    }
}

// ---------------- launch ---------------------------------------------------
extern "C" void kernel_launch(void* const* d_in, const int* in_sizes, int n_in,
                              void* d_out, int out_size) {
    const float* x   = (const float*)d_in[0];
    const float* src = (const float*)d_in[1];
    const float* Wq  = (const float*)d_in[2];
    const float* Wk  = (const float*)d_in[3];
    const float* Wv  = (const float*)d_in[4];
    const float* Wm  = (const float*)d_in[5];
    const float* W1  = (const float*)d_in[6];
    const float* W2  = (const float*)d_in[7];
    const float* g1  = (const float*)d_in[8];
    const float* b1  = (const float*)d_in[9];
    const float* g2  = (const float*)d_in[10];
    const float* b2  = (const float*)d_in[11];
    float* out = (float*)d_out;

    float* qfeat; cudaGetSymbolAddress((void**)&qfeat, g_qfeat);
    float* kfeat; cudaGetSymbolAddress((void**)&kfeat, g_kfeat);
    float* vfeat; cudaGetSymbolAddress((void**)&vfeat, g_vfeat);
    ush *xh, *xl, *sh_, *sl, *ath, *atl, *mh, *ml, *hbh, *hbl;
    cudaGetSymbolAddress((void**)&xh, g_xh);   cudaGetSymbolAddress((void**)&xl, g_xl);
    cudaGetSymbolAddress((void**)&sh_, g_sh);  cudaGetSymbolAddress((void**)&sl, g_sl);
    cudaGetSymbolAddress((void**)&ath, g_ath); cudaGetSymbolAddress((void**)&atl, g_atl);
    cudaGetSymbolAddress((void**)&mh, g_mh);   cudaGetSymbolAddress((void**)&ml, g_ml);
    cudaGetSymbolAddress((void**)&hbh, g_hbh); cudaGetSymbolAddress((void**)&hbl, g_hbl);
    ush *Bqh, *Bkh, *Bvh, *Bmh, *B1h, *B2h;
    cudaGetSymbolAddress((void**)&Bqh, g_Bqh);
    cudaGetSymbolAddress((void**)&Bkh, g_Bkh);
    cudaGetSymbolAddress((void**)&Bvh, g_Bvh);
    cudaGetSymbolAddress((void**)&Bmh, g_Bmh);
    cudaGetSymbolAddress((void**)&B1h, g_B1h);
    cudaGetSymbolAddress((void**)&B2h, g_B2h);

    cudaFuncSetAttribute(gemm_cp<1, false, false>, cudaFuncAttributeMaxDynamicSharedMemorySize, SMEM_ALLOC);
    cudaFuncSetAttribute(gemm_cp<0, false, false>, cudaFuncAttributeMaxDynamicSharedMemorySize, SMEM_ALLOC);
    cudaFuncSetAttribute(gemm_cp<3, false, true>,  cudaFuncAttributeMaxDynamicSharedMemorySize, SMEM_ALLOC);
    cudaFuncSetAttribute(gemm_cp<2, true, true>,   cudaFuncAttributeMaxDynamicSharedMemorySize, SMEM_ALLOC);
    cudaFuncSetAttribute(gemm_cp<4, false, false>, cudaFuncAttributeMaxDynamicSharedMemorySize, SMEM_ALLOC);

    const int n4 = MROWS * DD / 4;
    conv_pair<<<(n4 + 255) / 256, 256>>>(x,   xh,  xl,  n4);
    conv_pair<<<(n4 + 255) / 256, 256>>>(src, sh_, sl,  n4);
    conv_w<<<dim3(DD / 32, DD / 32), 256>>>(Wq, Bqh, DD, DD);
    conv_w<<<dim3(DD / 32, DD / 32), 256>>>(Wk, Bkh, DD, DD);
    conv_w<<<dim3(DD / 32, DD / 32), 256>>>(Wv, Bvh, DD, DD);
    conv_w<<<dim3(DD / 32, DD / 32), 256>>>(Wm, Bmh, DD, DD);
    conv_w<<<dim3(2 * DD / 32, 2 * DD / 32), 256>>>(W1, B1h, 2 * DD, 2 * DD);
    conv_w<<<dim3(DD / 32, 2 * DD / 32), 256>>>(W2, B2h, 2 * DD, DD);

    const dim3 gA(MROWS / 128, 1);
    const dim3 gW1(MROWS / 128, 2);

    gemm_cp<1, false, false><<<gA, 512, SMEM_ALLOC>>>(xh, xl, nullptr, nullptr, Bqh,
        qfeat, nullptr, nullptr, 256, 256, nullptr, nullptr, nullptr);
    gemm_cp<1, false, false><<<gA, 512, SMEM_ALLOC>>>(sh_, sl, nullptr, nullptr, Bkh,
        kfeat, nullptr, nullptr, 256, 256, nullptr, nullptr, nullptr);
    gemm_cp<0, false, false><<<gA, 512, SMEM_ALLOC>>>(sh_, sl, nullptr, nullptr, Bvh,
        vfeat, nullptr, nullptr, 256, 256, nullptr, nullptr, nullptr);

    kv_part<<<dim3(NB, HH, KSPLIT), 256>>>();
    kv_reduce<<<NB * HH, 256>>>();
    attn_kernel<<<MROWS / 8, 256>>>();

    gemm_cp<3, false, true><<<gA, 512, SMEM_ALLOC>>>(ath, atl, nullptr, nullptr, Bmh,
        nullptr, mh, ml, 256, 256, g1, b1, nullptr);
    gemm_cp<2, true, true><<<gW1, 512, SMEM_ALLOC>>>(xh, xl, mh, ml, B1h,
        nullptr, hbh, hbl, 512, 512, nullptr, nullptr, nullptr);
    gemm_cp<4, false, false><<<gA, 512, SMEM_ALLOC>>>(hbh, hbl, nullptr, nullptr, B2h,
        out, nullptr, nullptr, 512, 256, g2, b2, x);
}

// round 6
// speedup vs baseline: 4.3633x; 1.3759x over previous
#include <cuda_runtime.h>
#include <cuda_fp16.h>
#include <math.h>
#include <stdint.h>

#define NB 4
#define LL 8192
#define DD 256
#define HH 8
#define DHD 32
#define MROWS (NB * LL)   // 32768
#define KSPLIT 32

typedef unsigned short ush;

// ---------------- scratch (static device globals) --------------------------
__device__ float g_qfeat[MROWS * DD];
__device__ float g_kfeat[MROWS * DD];
__device__ float g_vfeat[MROWS * DD];
__device__ float g_KV   [NB * HH * DHD * DHD];
__device__ float g_Ksum [NB * HH * DHD];
__device__ float g_KVp  [NB * HH * KSPLIT * DHD * DHD];
__device__ float g_Ksp  [NB * HH * KSPLIT * DHD];
// fp16 operands
__device__ ush g_xh[MROWS * DD];
__device__ ush g_sh[MROWS * DD];
__device__ ush g_ath[MROWS * DD];
__device__ ush g_mh[MROWS * DD];
__device__ ush g_hbh[MROWS * 2 * DD];
// transposed fp16 weights [N][K]
__device__ ush g_Bqh[DD * DD];
__device__ ush g_Bkh[DD * DD];
__device__ ush g_Bvh[DD * DD];
__device__ ush g_Bmh[DD * DD];
__device__ ush g_B1h[2 * DD * 2 * DD];
__device__ ush g_B2h[2 * DD * DD];

// ---------------- helpers --------------------------------------------------
__device__ __forceinline__ uint32_t smem_u32(const void* p) {
    uint32_t a;
    asm("{ .reg .u64 t; cvta.to.shared.u64 t, %1; cvt.u32.u64 %0, t; }" : "=r"(a) : "l"(p));
    return a;
}
__device__ __forceinline__ void cp16(uint32_t dst, const void* src) {
    asm volatile("cp.async.cg.shared.global [%0], [%1], 16;" :: "r"(dst), "l"(src) : "memory");
}
__device__ __forceinline__ void ldsm4(uint32_t* r, uint32_t addr) {
    asm volatile("ldmatrix.sync.aligned.m8n8.x4.shared.b16 {%0,%1,%2,%3}, [%4];"
                 : "=r"(r[0]), "=r"(r[1]), "=r"(r[2]), "=r"(r[3]) : "r"(addr));
}
__device__ __forceinline__ void mma16816(float* c, const uint32_t* a, uint32_t b0, uint32_t b1) {
    asm volatile(
        "mma.sync.aligned.m16n8k16.row.col.f32.f16.f16.f32 "
        "{%0,%1,%2,%3}, {%4,%5,%6,%7}, {%8,%9}, {%0,%1,%2,%3};"
        : "+f"(c[0]), "+f"(c[1]), "+f"(c[2]), "+f"(c[3])
        : "r"(a[0]), "r"(a[1]), "r"(a[2]), "r"(a[3]), "r"(b0), "r"(b1));
}

// smem: stage = A 16K | B 32K = 48KB, 3 stages = 144KB
#define STG 49152
#define OFF_B  16384
#define STAGE_F 260
#define EX_OFF 135168
#define SMEM_ALLOC 147456

// 128B rows, 8 x 16B chunks, xor-swizzled
__device__ __forceinline__ uint32_t swz128(int r, int c) {
    return (uint32_t)(r * 128 + ((c ^ (r & 7)) << 4));
}

// ---------------- cp.async pipelined fp16 GEMM -----------------------------
// EPI: 0 none, 1 elu+1, 2 leaky, 3 LN(g,b), 4 LN + residual
template <int EPI, bool CONCAT, bool OUTH>
__global__ __launch_bounds__(512, 1)
void gemm_cp(const ush* __restrict__ Ah, const ush* __restrict__ A2h,
             const ush* __restrict__ Bh,
             float* __restrict__ Cf, ush* __restrict__ Ch,
             int kTot, int nFull,
             const float* __restrict__ g, const float* __restrict__ b,
             const float* __restrict__ xres) {
    extern __shared__ char smem[];
    const uint32_t sb = smem_u32(smem);
    const int t = threadIdx.x, lane = t & 31, wid = t >> 5;
    const int wm = wid & 3, wn = wid >> 2;
    const int mrow0 = blockIdx.x * 128;
    const int bcol = blockIdx.y * 256;
    const int NC = kTot >> 6;
    const int aStride = CONCAT ? 256 : kTot;

    float acc[2][8][4];
#pragma unroll
    for (int i = 0; i < 2; i++)
#pragma unroll
        for (int j = 0; j < 8; j++)
#pragma unroll
            for (int q = 0; q < 4; q++) acc[i][j][q] = 0.f;

#define ISSUE(icv)                                                               \
    {                                                                            \
        const int _ic = (icv);                                                   \
        if (_ic < NC) {                                                          \
            const int k0 = _ic * 64;                                             \
            const uint32_t base = sb + (_ic % 3) * STG;                          \
            const ush* pah;                                                      \
            int ka = k0;                                                         \
            if (CONCAT && k0 >= 256) { pah = A2h; ka = k0 - 256; }               \
            else { pah = Ah; }                                                   \
            _Pragma("unroll")                                                    \
            for (int _i = 0; _i < 2; _i++) {                                     \
                const int idx = t + _i * 512;                                    \
                const int r = idx >> 3, c = idx & 7;                             \
                cp16(base + swz128(r, c),                                        \
                     pah + (size_t)(mrow0 + r) * aStride + ka + c * 8);          \
            }                                                                    \
            _Pragma("unroll")                                                    \
            for (int _i = 0; _i < 4; _i++) {                                     \
                const int idx = t + _i * 512;                                    \
                const int rb = idx >> 3, cb = idx & 7;                           \
                cp16(base + OFF_B + swz128(rb, cb),                              \
                     Bh + (size_t)(bcol + rb) * kTot + k0 + cb * 8);             \
            }                                                                    \
        }                                                                        \
        asm volatile("cp.async.commit_group;" ::: "memory");                     \
    }

    ISSUE(0);
    ISSUE(1);

    const int lr = lane & 15, lh = lane >> 4;
    for (int ic = 0; ic < NC; ic++) {
        asm volatile("cp.async.wait_group 1;" ::: "memory");
        __syncthreads();
        ISSUE(ic + 2);
        const uint32_t sA32 = sb + (ic % 3) * STG;
        const uint32_t sB32 = sA32 + OFF_B;
#pragma unroll
        for (int ks = 0; ks < 4; ks++) {
            uint32_t AF[2][4], Bf[4][4];
#pragma unroll
            for (int i = 0; i < 2; i++) {
                const int r = wm * 32 + i * 16 + lr;
                ldsm4(AF[i], sA32 + swz128(r, ks * 2 + lh));
            }
#pragma unroll
            for (int j2 = 0; j2 < 4; j2++) {
                const int n = wn * 64 + j2 * 16 + lr;
                ldsm4(Bf[j2], sB32 + swz128(n, ks * 2 + lh));
            }
#pragma unroll
            for (int i = 0; i < 2; i++)
#pragma unroll
                for (int j2 = 0; j2 < 4; j2++) {
                    mma16816(acc[i][2 * j2 + 0], AF[i], Bf[j2][0], Bf[j2][2]);
                    mma16816(acc[i][2 * j2 + 1], AF[i], Bf[j2][1], Bf[j2][3]);
                }
        }
        __syncthreads();
    }
#undef ISSUE

    // ---- epilogue: frags -> smem staging ----
    float* stage = (float*)smem;
    {
        const int lr4 = lane >> 2, lc = (lane & 3) * 2;
#pragma unroll
        for (int i = 0; i < 2; i++) {
            const int r = wm * 32 + i * 16 + lr4;
#pragma unroll
            for (int j = 0; j < 8; j++) {
                const int c = wn * 64 + j * 8 + lc;
                *(float2*)&stage[r * STAGE_F + c] = make_float2(acc[i][j][0], acc[i][j][1]);
                *(float2*)&stage[(r + 8) * STAGE_F + c] = make_float2(acc[i][j][2], acc[i][j][3]);
            }
        }
    }
    __syncthreads();

    float* meanA = (float*)(smem + EX_OFF);
    float* rstdA = (float*)(smem + EX_OFF + 512);
    if (EPI >= 3) {
        if (t < 128) {
            float s1 = 0.f, s2 = 0.f;
#pragma unroll 8
            for (int c = 0; c < 256; c += 4) {
                float4 v = *(float4*)(stage + t * STAGE_F + c);
                s1 += v.x + v.y + v.z + v.w;
                s2 += v.x * v.x + v.y * v.y + v.z * v.z + v.w * v.w;
            }
            const float m = s1 * (1.f / 256.f);
            const float var = s2 * (1.f / 256.f) - m * m;
            meanA[t] = m;
            rstdA[t] = rsqrtf(var + 1e-5f);
        }
        __syncthreads();
    }

#pragma unroll 4
    for (int q = 0; q < 16; q++) {
        const int f = q * 512 + t;
        const int r = f >> 6, c = (f & 63) * 4;
        float4 v = *(float4*)(stage + r * STAGE_F + c);
        if (EPI == 1) {
            v.x = v.x > 0.f ? v.x + 1.f : expf(v.x);
            v.y = v.y > 0.f ? v.y + 1.f : expf(v.y);
            v.z = v.z > 0.f ? v.z + 1.f : expf(v.z);
            v.w = v.w > 0.f ? v.w + 1.f : expf(v.w);
        } else if (EPI == 2) {
            v.x = v.x >= 0.f ? v.x : 0.1f * v.x;
            v.y = v.y >= 0.f ? v.y : 0.1f * v.y;
            v.z = v.z >= 0.f ? v.z : 0.1f * v.z;
            v.w = v.w >= 0.f ? v.w : 0.1f * v.w;
        } else if (EPI >= 3) {
            const float m = meanA[r], rs = rstdA[r];
            float4 gv = *(const float4*)(g + bcol + c);
            float4 bv = *(const float4*)(b + bcol + c);
            v.x = (v.x - m) * rs * gv.x + bv.x;
            v.y = (v.y - m) * rs * gv.y + bv.y;
            v.z = (v.z - m) * rs * gv.z + bv.z;
            v.w = (v.w - m) * rs * gv.w + bv.w;
            if (EPI == 4) {
                float4 xr = *(const float4*)(xres + (size_t)(mrow0 + r) * 256 + c);
                v.x += xr.x; v.y += xr.y; v.z += xr.z; v.w += xr.w;
            }
        }
        if (OUTH) {
            const size_t o = (size_t)(mrow0 + r) * nFull + bcol + c;
            *(ushort4*)(Ch + o) = make_ushort4(
                __half_as_ushort(__float2half_rn(v.x)),
                __half_as_ushort(__float2half_rn(v.y)),
                __half_as_ushort(__float2half_rn(v.z)),
                __half_as_ushort(__float2half_rn(v.w)));
        } else {
            *(float4*)(Cf + (size_t)(mrow0 + r) * nFull + bcol + c) = v;
        }
    }
}

// ---------------- conversion kernels ---------------------------------------
__global__ __launch_bounds__(256)
void conv_h(const float* __restrict__ in, ush* __restrict__ hi, int n4) {
    const int i = blockIdx.x * 256 + threadIdx.x;
    if (i < n4) {
        float4 v = ((const float4*)in)[i];
        ((ushort4*)hi)[i] = make_ushort4(
            __half_as_ushort(__float2half_rn(v.x)),
            __half_as_ushort(__float2half_rn(v.y)),
            __half_as_ushort(__float2half_rn(v.z)),
            __half_as_ushort(__float2half_rn(v.w)));
    }
}

__global__ __launch_bounds__(256)
void conv_w(const float* __restrict__ W, ush* __restrict__ Bh, int K, int N) {
    __shared__ float tile[32][33];
    const int n0 = blockIdx.x * 32, k0 = blockIdx.y * 32;
    const int tx = threadIdx.x & 31, ty = threadIdx.x >> 5;
#pragma unroll
    for (int j = 0; j < 4; j++)
        tile[ty * 4 + j][tx] = W[(size_t)(k0 + ty * 4 + j) * N + n0 + tx];
    __syncthreads();
#pragma unroll
    for (int j = 0; j < 4; j++) {
        const int nl = ty * 4 + j;
        Bh[(size_t)(n0 + nl) * K + k0 + tx] =
            __half_as_ushort(__float2half_rn(tile[tx][nl]));
    }
}

// ---------------- KV partial -----------------------------------------------
__global__ __launch_bounds__(256)
void kv_part() {
    const int n = blockIdx.x, h = blockIdx.y, z = blockIdx.z;
    const float* Kf = g_kfeat + (size_t)n * LL * DD + h * DHD;
    const float* Vf = g_vfeat + (size_t)n * LL * DD + h * DHD;
    __shared__ float sh[4096];
    float* Ks = sh;
    float* Vs = sh + 2048;
    const int tid = threadIdx.x;
    const int sp = tid >> 6;
    const int rem = tid & 63;
    const int d0 = (rem >> 3) * 4;
    const int v0 = (rem & 7) * 4;
    float acc[4][4];
    float ksm[4] = {0.f, 0.f, 0.f, 0.f};
#pragma unroll
    for (int i = 0; i < 4; i++)
#pragma unroll
        for (int j = 0; j < 4; j++) acc[i][j] = 0.f;

    const int s_beg = z * (LL / KSPLIT);
    for (int s0 = s_beg; s0 < s_beg + (LL / KSPLIT); s0 += 64) {
#pragma unroll
        for (int i = 0; i < 2; i++) {
            const int f = tid * 2 + i;
            const int r = f >> 3;
            const int c4 = (f & 7) * 4;
            *(float4*)&Ks[r * 32 + c4] = *(const float4*)&Kf[(size_t)(s0 + r) * DD + c4];
            *(float4*)&Vs[r * 32 + c4] = *(const float4*)&Vf[(size_t)(s0 + r) * DD + c4];
        }
        __syncthreads();
#pragma unroll 4
        for (int s = sp; s < 64; s += 4) {
            float4 vv = *(const float4*)&Vs[s * 32 + v0];
#pragma unroll
            for (int i = 0; i < 4; i++) {
                const float kk = Ks[s * 32 + d0 + i];
                acc[i][0] += kk * vv.x;
                acc[i][1] += kk * vv.y;
                acc[i][2] += kk * vv.z;
                acc[i][3] += kk * vv.w;
                ksm[i] += kk;
            }
        }
        __syncthreads();
    }
    float* red = sh;
#pragma unroll
    for (int i = 0; i < 4; i++)
#pragma unroll
        for (int j = 0; j < 4; j++) red[tid * 16 + i * 4 + j] = acc[i][j];
    __syncthreads();
    const int p = (n * HH + h) * KSPLIT + z;
    if (sp == 0) {
        float* out = g_KVp + (size_t)p * 1024;
#pragma unroll
        for (int i = 0; i < 4; i++)
#pragma unroll
            for (int j = 0; j < 4; j++) {
                float s = red[rem * 16 + i * 4 + j] + red[(64 + rem) * 16 + i * 4 + j]
                        + red[(128 + rem) * 16 + i * 4 + j] + red[(192 + rem) * 16 + i * 4 + j];
                out[(d0 + i) * 32 + v0 + j] = s;
            }
    }
    __syncthreads();
#pragma unroll
    for (int i = 0; i < 4; i++) red[tid * 4 + i] = ksm[i];
    __syncthreads();
    if (sp == 0 && (rem & 7) == 0) {
#pragma unroll
        for (int i = 0; i < 4; i++) {
            float s = red[rem * 4 + i] + red[(64 + rem) * 4 + i]
                    + red[(128 + rem) * 4 + i] + red[(192 + rem) * 4 + i];
            g_Ksp[(size_t)p * 32 + d0 + i] = s;
        }
    }
}

__global__ __launch_bounds__(256)
void kv_reduce() {
    const int bh = blockIdx.x;
    for (int idx = threadIdx.x; idx < 1024; idx += 256) {
        float s = 0.f;
#pragma unroll 8
        for (int z = 0; z < KSPLIT; z++)
            s += g_KVp[((size_t)bh * KSPLIT + z) * 1024 + idx];
        g_KV[(size_t)bh * 1024 + idx] = s;
    }
    if (threadIdx.x < 32) {
        float s = 0.f;
#pragma unroll 8
        for (int z = 0; z < KSPLIT; z++)
            s += g_Ksp[((size_t)bh * KSPLIT + z) * 32 + threadIdx.x];
        g_Ksum[bh * 32 + threadIdx.x] = s;
    }
}

// ---------------- per-token message (outputs fp16) -------------------------
__global__ __launch_bounds__(256)
void attn_kernel() {
    __shared__ float KVs[HH * DHD * DHD];
    __shared__ float Kss[HH * DHD];
    const int tid = threadIdx.x;
    const int tok0 = blockIdx.x * 8;
    const int n = tok0 / LL;
    const float* KVg = g_KV + (size_t)n * HH * DHD * DHD;
    for (int i = tid; i < HH * DHD * DHD; i += 256) KVs[i] = KVg[i];
    for (int i = tid; i < HH * DHD; i += 256) Kss[i] = g_Ksum[(size_t)n * HH * DHD + i];
    __syncthreads();

    const int warp = tid >> 5, lane = tid & 31;
    const int tok = tok0 + warp;
    const float* Q = g_qfeat + (size_t)tok * DD;
    float q[HH];
#pragma unroll
    for (int h = 0; h < HH; h++) q[h] = Q[h * DHD + lane];

#pragma unroll
    for (int h = 0; h < HH; h++) {
        float p = q[h] * Kss[h * DHD + lane];
#pragma unroll
        for (int o = 16; o > 0; o >>= 1) p += __shfl_xor_sync(0xffffffffu, p, o);
        const float z = 1.f / (p + 1e-6f);
        float acc = 0.f;
#pragma unroll
        for (int dd = 0; dd < DHD; dd++)
            acc += __shfl_sync(0xffffffffu, q[h], dd) * KVs[h * DHD * DHD + dd * DHD + lane];
        g_ath[(size_t)tok * DD + h * DHD + lane] =
            __half_as_ushort(__float2half_rn(acc * z));
    }
}

// ---------------- launch ---------------------------------------------------
extern "C" void kernel_launch(void* const* d_in, const int* in_sizes, int n_in,
                              void* d_out, int out_size) {
    const float* x   = (const float*)d_in[0];
    const float* src = (const float*)d_in[1];
    const float* Wq  = (const float*)d_in[2];
    const float* Wk  = (const float*)d_in[3];
    const float* Wv  = (const float*)d_in[4];
    const float* Wm  = (const float*)d_in[5];
    const float* W1  = (const float*)d_in[6];
    const float* W2  = (const float*)d_in[7];
    const float* g1  = (const float*)d_in[8];
    const float* b1  = (const float*)d_in[9];
    const float* g2  = (const float*)d_in[10];
    const float* b2  = (const float*)d_in[11];
    float* out = (float*)d_out;

    float* qfeat; cudaGetSymbolAddress((void**)&qfeat, g_qfeat);
    float* kfeat; cudaGetSymbolAddress((void**)&kfeat, g_kfeat);
    float* vfeat; cudaGetSymbolAddress((void**)&vfeat, g_vfeat);
    ush *xh, *sh_, *ath, *mh, *hbh;
    cudaGetSymbolAddress((void**)&xh, g_xh);
    cudaGetSymbolAddress((void**)&sh_, g_sh);
    cudaGetSymbolAddress((void**)&ath, g_ath);
    cudaGetSymbolAddress((void**)&mh, g_mh);
    cudaGetSymbolAddress((void**)&hbh, g_hbh);
    ush *Bqh, *Bkh, *Bvh, *Bmh, *B1h, *B2h;
    cudaGetSymbolAddress((void**)&Bqh, g_Bqh);
    cudaGetSymbolAddress((void**)&Bkh, g_Bkh);
    cudaGetSymbolAddress((void**)&Bvh, g_Bvh);
    cudaGetSymbolAddress((void**)&Bmh, g_Bmh);
    cudaGetSymbolAddress((void**)&B1h, g_B1h);
    cudaGetSymbolAddress((void**)&B2h, g_B2h);

    cudaFuncSetAttribute(gemm_cp<1, false, false>, cudaFuncAttributeMaxDynamicSharedMemorySize, SMEM_ALLOC);
    cudaFuncSetAttribute(gemm_cp<0, false, false>, cudaFuncAttributeMaxDynamicSharedMemorySize, SMEM_ALLOC);
    cudaFuncSetAttribute(gemm_cp<3, false, true>,  cudaFuncAttributeMaxDynamicSharedMemorySize, SMEM_ALLOC);
    cudaFuncSetAttribute(gemm_cp<2, true, true>,   cudaFuncAttributeMaxDynamicSharedMemorySize, SMEM_ALLOC);
    cudaFuncSetAttribute(gemm_cp<4, false, false>, cudaFuncAttributeMaxDynamicSharedMemorySize, SMEM_ALLOC);

    const int n4 = MROWS * DD / 4;
    conv_h<<<(n4 + 255) / 256, 256>>>(x,   xh,  n4);
    conv_h<<<(n4 + 255) / 256, 256>>>(src, sh_, n4);
    conv_w<<<dim3(DD / 32, DD / 32), 256>>>(Wq, Bqh, DD, DD);
    conv_w<<<dim3(DD / 32, DD / 32), 256>>>(Wk, Bkh, DD, DD);
    conv_w<<<dim3(DD / 32, DD / 32), 256>>>(Wv, Bvh, DD, DD);
    conv_w<<<dim3(DD / 32, DD / 32), 256>>>(Wm, Bmh, DD, DD);
    conv_w<<<dim3(2 * DD / 32, 2 * DD / 32), 256>>>(W1, B1h, 2 * DD, 2 * DD);
    conv_w<<<dim3(DD / 32, 2 * DD / 32), 256>>>(W2, B2h, 2 * DD, DD);

    const dim3 gA(MROWS / 128, 1);
    const dim3 gW1(MROWS / 128, 2);

    gemm_cp<1, false, false><<<gA, 512, SMEM_ALLOC>>>(xh, nullptr, Bqh,
        qfeat, nullptr, 256, 256, nullptr, nullptr, nullptr);
    gemm_cp<1, false, false><<<gA, 512, SMEM_ALLOC>>>(sh_, nullptr, Bkh,
        kfeat, nullptr, 256, 256, nullptr, nullptr, nullptr);
    gemm_cp<0, false, false><<<gA, 512, SMEM_ALLOC>>>(sh_, nullptr, Bvh,
        vfeat, nullptr, 256, 256, nullptr, nullptr, nullptr);

    kv_part<<<dim3(NB, HH, KSPLIT), 256>>>();
    kv_reduce<<<NB * HH, 256>>>();
    attn_kernel<<<MROWS / 8, 256>>>();

    gemm_cp<3, false, true><<<gA, 512, SMEM_ALLOC>>>(ath, nullptr, Bmh,
        nullptr, mh, 256, 256, g1, b1, nullptr);
    gemm_cp<2, true, true><<<gW1, 512, SMEM_ALLOC>>>(xh, mh, B1h,
        nullptr, hbh, 512, 512, nullptr, nullptr, nullptr);
    gemm_cp<4, false, false><<<gA, 512, SMEM_ALLOC>>>(hbh, nullptr, B2h,
        out, nullptr, 512, 256, g2, b2, x);
}

// round 7
// speedup vs baseline: 4.7564x; 1.0901x over previous
#include <cuda_runtime.h>
#include <cuda_fp16.h>
#include <math.h>
#include <stdint.h>

#define NB 4
#define LL 8192
#define DD 256
#define HH 8
#define DHD 32
#define MROWS (NB * LL)   // 32768
#define KSPLIT 32

typedef unsigned short ush;

// ---------------- scratch (static device globals) --------------------------
__device__ float g_KV   [NB * HH * DHD * DHD];
__device__ float g_Ksum [NB * HH * DHD];
__device__ float g_KVp  [NB * HH * KSPLIT * DHD * DHD];
__device__ float g_Ksp  [NB * HH * KSPLIT * DHD];
// fp16 operands
__device__ ush g_xh [MROWS * DD];
__device__ ush g_sh [MROWS * DD];
__device__ ush g_qf [MROWS * DD];      // Q features fp16
__device__ ush g_kf [MROWS * DD];      // K features fp16
__device__ ush g_vf [MROWS * DD];      // V features fp16
__device__ ush g_ath[MROWS * DD];
__device__ ush g_mh [MROWS * DD];
__device__ ush g_hbh[MROWS * 2 * DD];
// transposed fp16 weights [N][K]
__device__ ush g_Bqh[DD * DD];
__device__ ush g_Bkh[DD * DD];
__device__ ush g_Bvh[DD * DD];
__device__ ush g_Bmh[DD * DD];
__device__ ush g_B1h[2 * DD * 2 * DD];
__device__ ush g_B2h[2 * DD * DD];

// ---------------- helpers --------------------------------------------------
__device__ __forceinline__ uint32_t smem_u32(const void* p) {
    uint32_t a;
    asm("{ .reg .u64 t; cvta.to.shared.u64 t, %1; cvt.u32.u64 %0, t; }" : "=r"(a) : "l"(p));
    return a;
}
__device__ __forceinline__ void cp16(uint32_t dst, const void* src) {
    asm volatile("cp.async.cg.shared.global [%0], [%1], 16;" :: "r"(dst), "l"(src) : "memory");
}
__device__ __forceinline__ void ldsm4(uint32_t* r, uint32_t addr) {
    asm volatile("ldmatrix.sync.aligned.m8n8.x4.shared.b16 {%0,%1,%2,%3}, [%4];"
                 : "=r"(r[0]), "=r"(r[1]), "=r"(r[2]), "=r"(r[3]) : "r"(addr));
}
__device__ __forceinline__ void mma16816(float* c, const uint32_t* a, uint32_t b0, uint32_t b1) {
    asm volatile(
        "mma.sync.aligned.m16n8k16.row.col.f32.f16.f16.f32 "
        "{%0,%1,%2,%3}, {%4,%5,%6,%7}, {%8,%9}, {%0,%1,%2,%3};"
        : "+f"(c[0]), "+f"(c[1]), "+f"(c[2]), "+f"(c[3])
        : "r"(a[0]), "r"(a[1]), "r"(a[2]), "r"(a[3]), "r"(b0), "r"(b1));
}
__device__ __forceinline__ ush f2h(float v) {
    return __half_as_ushort(__float2half_rn(v));
}

// 128B rows, 8 x 16B chunks, xor-swizzled
__device__ __forceinline__ uint32_t swz128(int r, int c) {
    return (uint32_t)(r * 128 + ((c ^ (r & 7)) << 4));
}

// ---------------- cp.async pipelined fp16 GEMM -----------------------------
// Tile: 128 x BN. BN=128 -> 256 thr / occ 2;  BN=256 -> 512 thr / occ 1 (LN ok)
// EPI: 0 none, 1 elu+1, 2 leaky, 3 LN(g,b), 4 LN + residual
template <int EPI, bool CONCAT, bool OUTH, int BN>
__global__ __launch_bounds__(BN == 128 ? 256 : 512, BN == 128 ? 2 : 1)
void gemm_cp(const ush* __restrict__ Ah, const ush* __restrict__ A2h,
             const ush* __restrict__ Bh,
             float* __restrict__ Cf, ush* __restrict__ Ch,
             int kTot, int nFull,
             const float* __restrict__ g, const float* __restrict__ b,
             const float* __restrict__ xres) {
    constexpr int THREADS = (BN == 128) ? 256 : 512;
    constexpr int STG = 16384 + BN * 128;        // A 16K + B (BN rows x 128B)
    constexpr int OFF_B = 16384;
    constexpr int STAGE_F = BN + 4;
    constexpr int A_IT = 1024 / THREADS;
    constexpr int B_IT = BN * 8 / THREADS;
    constexpr int NWN = BN / 64;

    extern __shared__ char smem[];
    const uint32_t sb = smem_u32(smem);
    const int t = threadIdx.x, lane = t & 31, wid = t >> 5;
    const int wm = wid & 3, wn = wid >> 2;       // wn < NWN
    const int mrow0 = blockIdx.x * 128;
    const int bcol = blockIdx.y * BN;
    const int NC = kTot >> 6;
    const int aStride = CONCAT ? 256 : kTot;

    float acc[2][8][4];
#pragma unroll
    for (int i = 0; i < 2; i++)
#pragma unroll
        for (int j = 0; j < 8; j++)
#pragma unroll
            for (int q = 0; q < 4; q++) acc[i][j][q] = 0.f;

#define ISSUE(icv)                                                               \
    {                                                                            \
        const int _ic = (icv);                                                   \
        if (_ic < NC) {                                                          \
            const int k0 = _ic * 64;                                             \
            const uint32_t base = sb + (_ic % 3) * STG;                          \
            const ush* pah;                                                      \
            int ka = k0;                                                         \
            if (CONCAT && k0 >= 256) { pah = A2h; ka = k0 - 256; }               \
            else { pah = Ah; }                                                   \
            _Pragma("unroll")                                                    \
            for (int _i = 0; _i < A_IT; _i++) {                                  \
                const int idx = t + _i * THREADS;                                \
                const int r = idx >> 3, c = idx & 7;                             \
                cp16(base + swz128(r, c),                                        \
                     pah + (size_t)(mrow0 + r) * aStride + ka + c * 8);          \
            }                                                                    \
            _Pragma("unroll")                                                    \
            for (int _i = 0; _i < B_IT; _i++) {                                  \
                const int idx = t + _i * THREADS;                                \
                const int rb = idx >> 3, cb = idx & 7;                           \
                cp16(base + OFF_B + swz128(rb, cb),                              \
                     Bh + (size_t)(bcol + rb) * kTot + k0 + cb * 8);             \
            }                                                                    \
        }                                                                        \
        asm volatile("cp.async.commit_group;" ::: "memory");                     \
    }

    ISSUE(0);
    ISSUE(1);

    const int lr = lane & 15, lh = lane >> 4;
    for (int ic = 0; ic < NC; ic++) {
        asm volatile("cp.async.wait_group 1;" ::: "memory");
        __syncthreads();
        ISSUE(ic + 2);
        const uint32_t sA32 = sb + (ic % 3) * STG;
        const uint32_t sB32 = sA32 + OFF_B;
#pragma unroll
        for (int ks = 0; ks < 4; ks++) {
            uint32_t AF[2][4], Bf[4][4];
#pragma unroll
            for (int i = 0; i < 2; i++) {
                const int r = wm * 32 + i * 16 + lr;
                ldsm4(AF[i], sA32 + swz128(r, ks * 2 + lh));
            }
#pragma unroll
            for (int j2 = 0; j2 < 4; j2++) {
                const int n = wn * 64 + j2 * 16 + lr;
                ldsm4(Bf[j2], sB32 + swz128(n, ks * 2 + lh));
            }
#pragma unroll
            for (int i = 0; i < 2; i++)
#pragma unroll
                for (int j2 = 0; j2 < 4; j2++) {
                    mma16816(acc[i][2 * j2 + 0], AF[i], Bf[j2][0], Bf[j2][2]);
                    mma16816(acc[i][2 * j2 + 1], AF[i], Bf[j2][1], Bf[j2][3]);
                }
        }
        __syncthreads();
    }
#undef ISSUE

    // ---- epilogue: frags -> smem staging ----
    float* stage = (float*)smem;
    {
        const int lr4 = lane >> 2, lc = (lane & 3) * 2;
#pragma unroll
        for (int i = 0; i < 2; i++) {
            const int r = wm * 32 + i * 16 + lr4;
#pragma unroll
            for (int j = 0; j < 8; j++) {
                const int c = wn * 64 + j * 8 + lc;
                *(float2*)&stage[r * STAGE_F + c] = make_float2(acc[i][j][0], acc[i][j][1]);
                *(float2*)&stage[(r + 8) * STAGE_F + c] = make_float2(acc[i][j][2], acc[i][j][3]);
            }
        }
    }
    __syncthreads();

    float* meanA = (float*)(smem + 128 * STAGE_F * 4);
    float* rstdA = meanA + 128;
    if (EPI >= 3) {
        if (t < 128) {
            float s1 = 0.f, s2 = 0.f;
#pragma unroll 8
            for (int c = 0; c < 256; c += 4) {
                float4 v = *(float4*)(stage + t * STAGE_F + c);
                s1 += v.x + v.y + v.z + v.w;
                s2 += v.x * v.x + v.y * v.y + v.z * v.z + v.w * v.w;
            }
            const float m = s1 * (1.f / 256.f);
            const float var = s2 * (1.f / 256.f) - m * m;
            meanA[t] = m;
            rstdA[t] = rsqrtf(var + 1e-5f);
        }
        __syncthreads();
    }

#pragma unroll 4
    for (int q = 0; q < 16; q++) {
        const int f = q * THREADS + t;
        const int r = f / (BN / 4), c = (f % (BN / 4)) * 4;
        float4 v = *(float4*)(stage + r * STAGE_F + c);
        if (EPI == 1) {
            v.x = v.x > 0.f ? v.x + 1.f : expf(v.x);
            v.y = v.y > 0.f ? v.y + 1.f : expf(v.y);
            v.z = v.z > 0.f ? v.z + 1.f : expf(v.z);
            v.w = v.w > 0.f ? v.w + 1.f : expf(v.w);
        } else if (EPI == 2) {
            v.x = v.x >= 0.f ? v.x : 0.1f * v.x;
            v.y = v.y >= 0.f ? v.y : 0.1f * v.y;
            v.z = v.z >= 0.f ? v.z : 0.1f * v.z;
            v.w = v.w >= 0.f ? v.w : 0.1f * v.w;
        } else if (EPI >= 3) {
            const float m = meanA[r], rs = rstdA[r];
            float4 gv = *(const float4*)(g + bcol + c);
            float4 bv = *(const float4*)(b + bcol + c);
            v.x = (v.x - m) * rs * gv.x + bv.x;
            v.y = (v.y - m) * rs * gv.y + bv.y;
            v.z = (v.z - m) * rs * gv.z + bv.z;
            v.w = (v.w - m) * rs * gv.w + bv.w;
            if (EPI == 4) {
                float4 xr = *(const float4*)(xres + (size_t)(mrow0 + r) * 256 + c);
                v.x += xr.x; v.y += xr.y; v.z += xr.z; v.w += xr.w;
            }
        }
        if (OUTH) {
            const size_t o = (size_t)(mrow0 + r) * nFull + bcol + c;
            *(ushort4*)(Ch + o) = make_ushort4(f2h(v.x), f2h(v.y), f2h(v.z), f2h(v.w));
        } else {
            *(float4*)(Cf + (size_t)(mrow0 + r) * nFull + bcol + c) = v;
        }
    }
}

#define SMEM128 98304    // 3 x 32KB (staging 128x132x4 = 67.6KB fits)
#define SMEM256 147456   // 3 x 48KB (staging 128x260x4 + LN extras fits)

// ---------------- merged conversion kernels --------------------------------
__global__ __launch_bounds__(256)
void conv_h2(const float* __restrict__ x, const float* __restrict__ s,
             ush* __restrict__ xh, ush* __restrict__ sh, int n4) {
    const int i = blockIdx.x * 256 + threadIdx.x;
    const float* in = blockIdx.y ? s : x;
    ush* outp = blockIdx.y ? sh : xh;
    if (i < n4) {
        float4 v = ((const float4*)in)[i];
        ((ushort4*)outp)[i] = make_ushort4(f2h(v.x), f2h(v.y), f2h(v.z), f2h(v.w));
    }
}

__global__ __launch_bounds__(256)
void conv_w_all(const float* Wq, const float* Wk, const float* Wv,
                const float* Wm, const float* W1, const float* W2,
                ush* Bq, ush* Bk, ush* Bv, ush* Bm, ush* B1, ush* B2) {
    const float* W; ush* B; int K, N;
    switch (blockIdx.z) {
        case 0: W = Wq; B = Bq; K = DD; N = DD; break;
        case 1: W = Wk; B = Bk; K = DD; N = DD; break;
        case 2: W = Wv; B = Bv; K = DD; N = DD; break;
        case 3: W = Wm; B = Bm; K = DD; N = DD; break;
        case 4: W = W1; B = B1; K = 2 * DD; N = 2 * DD; break;
        default: W = W2; B = B2; K = 2 * DD; N = DD; break;
    }
    if ((int)blockIdx.x >= N / 32 || (int)blockIdx.y >= K / 32) return;
    __shared__ float tile[32][33];
    const int n0 = blockIdx.x * 32, k0 = blockIdx.y * 32;
    const int tx = threadIdx.x & 31, ty = threadIdx.x >> 5;
#pragma unroll
    for (int j = 0; j < 4; j++)
        tile[ty * 4 + j][tx] = W[(size_t)(k0 + ty * 4 + j) * N + n0 + tx];
    __syncthreads();
#pragma unroll
    for (int j = 0; j < 4; j++) {
        const int nl = ty * 4 + j;
        B[(size_t)(n0 + nl) * K + k0 + tx] = f2h(tile[tx][nl]);
    }
}

// ---------------- KV partial (fp16 features) --------------------------------
__global__ __launch_bounds__(256)
void kv_part() {
    const int n = blockIdx.x, h = blockIdx.y, z = blockIdx.z;
    const ush* Kf = g_kf + (size_t)n * LL * DD + h * DHD;
    const ush* Vf = g_vf + (size_t)n * LL * DD + h * DHD;
    __shared__ float sh[4096];
    float* Ks = sh;
    float* Vs = sh + 2048;
    const int tid = threadIdx.x;
    const int sp = tid >> 6;
    const int rem = tid & 63;
    const int d0 = (rem >> 3) * 4;
    const int v0 = (rem & 7) * 4;
    float acc[4][4];
    float ksm[4] = {0.f, 0.f, 0.f, 0.f};
#pragma unroll
    for (int i = 0; i < 4; i++)
#pragma unroll
        for (int j = 0; j < 4; j++) acc[i][j] = 0.f;

    const int lr = tid >> 2, lc8 = (tid & 3) * 8;   // 64 rows x 4 chunks of 8
    const int s_beg = z * (LL / KSPLIT);
    for (int s0 = s_beg; s0 < s_beg + (LL / KSPLIT); s0 += 64) {
        {
            uint4 uk = *(const uint4*)&Kf[(size_t)(s0 + lr) * DD + lc8];
            uint4 uv = *(const uint4*)&Vf[(size_t)(s0 + lr) * DD + lc8];
            const __half2* hk = (const __half2*)&uk;
            const __half2* hv = (const __half2*)&uv;
#pragma unroll
            for (int j = 0; j < 4; j++) {
                float2 fk = __half22float2(hk[j]);
                float2 fv = __half22float2(hv[j]);
                Ks[lr * 32 + lc8 + 2 * j + 0] = fk.x;
                Ks[lr * 32 + lc8 + 2 * j + 1] = fk.y;
                Vs[lr * 32 + lc8 + 2 * j + 0] = fv.x;
                Vs[lr * 32 + lc8 + 2 * j + 1] = fv.y;
            }
        }
        __syncthreads();
#pragma unroll 4
        for (int s = sp; s < 64; s += 4) {
            float4 vv = *(const float4*)&Vs[s * 32 + v0];
#pragma unroll
            for (int i = 0; i < 4; i++) {
                const float kk = Ks[s * 32 + d0 + i];
                acc[i][0] += kk * vv.x;
                acc[i][1] += kk * vv.y;
                acc[i][2] += kk * vv.z;
                acc[i][3] += kk * vv.w;
                ksm[i] += kk;
            }
        }
        __syncthreads();
    }
    float* red = sh;
#pragma unroll
    for (int i = 0; i < 4; i++)
#pragma unroll
        for (int j = 0; j < 4; j++) red[tid * 16 + i * 4 + j] = acc[i][j];
    __syncthreads();
    const int p = (n * HH + h) * KSPLIT + z;
    if (sp == 0) {
        float* outp = g_KVp + (size_t)p * 1024;
#pragma unroll
        for (int i = 0; i < 4; i++)
#pragma unroll
            for (int j = 0; j < 4; j++) {
                float s = red[rem * 16 + i * 4 + j] + red[(64 + rem) * 16 + i * 4 + j]
                        + red[(128 + rem) * 16 + i * 4 + j] + red[(192 + rem) * 16 + i * 4 + j];
                outp[(d0 + i) * 32 + v0 + j] = s;
            }
    }
    __syncthreads();
#pragma unroll
    for (int i = 0; i < 4; i++) red[tid * 4 + i] = ksm[i];
    __syncthreads();
    if (sp == 0 && (rem & 7) == 0) {
#pragma unroll
        for (int i = 0; i < 4; i++) {
            float s = red[rem * 4 + i] + red[(64 + rem) * 4 + i]
                    + red[(128 + rem) * 4 + i] + red[(192 + rem) * 4 + i];
            g_Ksp[(size_t)p * 32 + d0 + i] = s;
        }
    }
}

__global__ __launch_bounds__(256)
void kv_reduce() {
    const int bh = blockIdx.x;
    for (int idx = threadIdx.x; idx < 1024; idx += 256) {
        float s = 0.f;
#pragma unroll 8
        for (int z = 0; z < KSPLIT; z++)
            s += g_KVp[((size_t)bh * KSPLIT + z) * 1024 + idx];
        g_KV[(size_t)bh * 1024 + idx] = s;
    }
    if (threadIdx.x < 32) {
        float s = 0.f;
#pragma unroll 8
        for (int z = 0; z < KSPLIT; z++)
            s += g_Ksp[((size_t)bh * KSPLIT + z) * 32 + threadIdx.x];
        g_Ksum[bh * 32 + threadIdx.x] = s;
    }
}

// ---------------- per-token message (fp16 in / fp16 out) -------------------
__global__ __launch_bounds__(256)
void attn_kernel() {
    __shared__ float KVs[HH * DHD * DHD];
    __shared__ float Kss[HH * DHD];
    const int tid = threadIdx.x;
    const int tok0 = blockIdx.x * 8;
    const int n = tok0 / LL;
    const float* KVg = g_KV + (size_t)n * HH * DHD * DHD;
    for (int i = tid; i < HH * DHD * DHD; i += 256) KVs[i] = KVg[i];
    for (int i = tid; i < HH * DHD; i += 256) Kss[i] = g_Ksum[(size_t)n * HH * DHD + i];
    __syncthreads();

    const int warp = tid >> 5, lane = tid & 31;
    const int tok = tok0 + warp;
    const ush* Q = g_qf + (size_t)tok * DD;
    float q[HH];
#pragma unroll
    for (int h = 0; h < HH; h++)
        q[h] = __half2float(__ushort_as_half(Q[h * DHD + lane]));

#pragma unroll
    for (int h = 0; h < HH; h++) {
        float p = q[h] * Kss[h * DHD + lane];
#pragma unroll
        for (int o = 16; o > 0; o >>= 1) p += __shfl_xor_sync(0xffffffffu, p, o);
        const float z = 1.f / (p + 1e-6f);
        float acc = 0.f;
#pragma unroll
        for (int dd = 0; dd < DHD; dd++)
            acc += __shfl_sync(0xffffffffu, q[h], dd) * KVs[h * DHD * DHD + dd * DHD + lane];
        g_ath[(size_t)tok * DD + h * DHD + lane] = f2h(acc * z);
    }
}

// ---------------- launch ---------------------------------------------------
extern "C" void kernel_launch(void* const* d_in, const int* in_sizes, int n_in,
                              void* d_out, int out_size) {
    const float* x   = (const float*)d_in[0];
    const float* src = (const float*)d_in[1];
    const float* Wq  = (const float*)d_in[2];
    const float* Wk  = (const float*)d_in[3];
    const float* Wv  = (const float*)d_in[4];
    const float* Wm  = (const float*)d_in[5];
    const float* W1  = (const float*)d_in[6];
    const float* W2  = (const float*)d_in[7];
    const float* g1  = (const float*)d_in[8];
    const float* b1  = (const float*)d_in[9];
    const float* g2  = (const float*)d_in[10];
    const float* b2  = (const float*)d_in[11];
    float* out = (float*)d_out;

    ush *xh, *sh_, *qf, *kf, *vf, *ath, *mh, *hbh;
    cudaGetSymbolAddress((void**)&xh, g_xh);
    cudaGetSymbolAddress((void**)&sh_, g_sh);
    cudaGetSymbolAddress((void**)&qf, g_qf);
    cudaGetSymbolAddress((void**)&kf, g_kf);
    cudaGetSymbolAddress((void**)&vf, g_vf);
    cudaGetSymbolAddress((void**)&ath, g_ath);
    cudaGetSymbolAddress((void**)&mh, g_mh);
    cudaGetSymbolAddress((void**)&hbh, g_hbh);
    ush *Bqh, *Bkh, *Bvh, *Bmh, *B1h, *B2h;
    cudaGetSymbolAddress((void**)&Bqh, g_Bqh);
    cudaGetSymbolAddress((void**)&Bkh, g_Bkh);
    cudaGetSymbolAddress((void**)&Bvh, g_Bvh);
    cudaGetSymbolAddress((void**)&Bmh, g_Bmh);
    cudaGetSymbolAddress((void**)&B1h, g_B1h);
    cudaGetSymbolAddress((void**)&B2h, g_B2h);

    cudaFuncSetAttribute(gemm_cp<1, false, true, 128>,  cudaFuncAttributeMaxDynamicSharedMemorySize, SMEM128);
    cudaFuncSetAttribute(gemm_cp<0, false, true, 128>,  cudaFuncAttributeMaxDynamicSharedMemorySize, SMEM128);
    cudaFuncSetAttribute(gemm_cp<2, true, true, 128>,   cudaFuncAttributeMaxDynamicSharedMemorySize, SMEM128);
    cudaFuncSetAttribute(gemm_cp<3, false, true, 256>,  cudaFuncAttributeMaxDynamicSharedMemorySize, SMEM256);
    cudaFuncSetAttribute(gemm_cp<4, false, false, 256>, cudaFuncAttributeMaxDynamicSharedMemorySize, SMEM256);

    // conversions (2 launches total)
    const int n4 = MROWS * DD / 4;
    conv_h2<<<dim3((n4 + 255) / 256, 2), 256>>>(x, src, xh, sh_, n4);
    conv_w_all<<<dim3(16, 16, 6), 256>>>(Wq, Wk, Wv, Wm, W1, W2,
                                         Bqh, Bkh, Bvh, Bmh, B1h, B2h);

    const dim3 gQKV(MROWS / 128, 2);   // BN=128
    const dim3 gW1(MROWS / 128, 4);    // BN=128
    const dim3 gLN(MROWS / 128, 1);    // BN=256

    // Q/K/V features -> fp16 (elu+1 for Q,K)
    gemm_cp<1, false, true, 128><<<gQKV, 256, SMEM128>>>(xh, nullptr, Bqh,
        nullptr, qf, 256, 256, nullptr, nullptr, nullptr);
    gemm_cp<1, false, true, 128><<<gQKV, 256, SMEM128>>>(sh_, nullptr, Bkh,
        nullptr, kf, 256, 256, nullptr, nullptr, nullptr);
    gemm_cp<0, false, true, 128><<<gQKV, 256, SMEM128>>>(sh_, nullptr, Bvh,
        nullptr, vf, 256, 256, nullptr, nullptr, nullptr);

    kv_part<<<dim3(NB, HH, KSPLIT), 256>>>();
    kv_reduce<<<NB * HH, 256>>>();
    attn_kernel<<<MROWS / 8, 256>>>();

    // merge heads + fused LN1 -> fp16
    gemm_cp<3, false, true, 256><<<gLN, 512, SMEM256>>>(ath, nullptr, Bmh,
        nullptr, mh, 256, 256, g1, b1, nullptr);
    // concat -> W1 (leaky) -> fp16
    gemm_cp<2, true, true, 128><<<gW1, 256, SMEM128>>>(xh, mh, B1h,
        nullptr, hbh, 512, 512, nullptr, nullptr, nullptr);
    // W2 + fused LN2 + residual -> out (fp32)
    gemm_cp<4, false, false, 256><<<gLN, 512, SMEM256>>>(hbh, nullptr, B2h,
        out, nullptr, 512, 256, g2, b2, x);
}